// round 6
// baseline (speedup 1.0000x reference)
#include <cuda_runtime.h>
#include <cuda_bf16.h>
#include <cstdint>
#include <math.h>

#define KK     15
#define HW     128
#define PLANE  16384
#define CIN    768
#define NSO    24
#define NF     48          // filters (N dim)
#define RT     4           // output rows per CTA
#define ARING  8           // TMEM A-chunk ring slots (16 cols each)
#define NCHUNK 18          // RT + 14 input rows per CTA

// ---- smem layout (bytes) for tcgen05 path ----
#define SM_TMEM   0
#define SM_MBAR   64                 // 15 mbarriers x 8B
#define SM_B      1024               // 4 B-slots x 6144B (48 rows x 128B, SW128)
#define SLOT_BF   6144
#define SM_X      (SM_B + 4*SLOT_BF) // 25600: 18 x-rows x 128 floats
// tcgen05 path needs ~34816; fallback needs 53568. Launch with max.
#define SMEM_GABOR 53568

// TMEM columns: D tiles at r*64 (r=0..3); A ring at 256 + slot*16 (slots 0..7)
#define TM_A0  256

// idesc kind::f16 bf16: dfmt=F32(1)<<4 | atype=BF16(1)<<7 | btype=BF16(1)<<10
//                        | (N/8)<<17 | (M/16)<<24
#define IDESC_BF16 ((1u<<4) | (1u<<7) | (1u<<10) | ((NF/8)<<17) | ((128/16)<<24))

#if defined(__CUDA_ARCH__) && (defined(__CUDA_ARCH_FEAT_SM103_ALL) || defined(__CUDA_ARCH_SPECIFIC__))
#define HAS_TCGEN05 1
#else
#define HAS_TCGEN05 0
#endif

typedef unsigned long long u64;

// Scratch (.bss)
__device__ float g_mag[(size_t)4 * CIN * PLANE];   // [b][c*24+so][y*128+x]
__device__ float g_z[(size_t)128 * PLANE];
__device__ float g_stats[256];

// ---------------- portable helpers ----------------
__device__ __forceinline__ u64 splat(float v) {
    u64 r; asm("mov.b64 %0, {%1,%1};" : "=l"(r) : "f"(v)); return r;
}
__device__ __forceinline__ void fma2(u64& d, u64 a, u64 b) {
    asm("fma.rn.f32x2 %0, %1, %2, %0;" : "+l"(d) : "l"(a), "l"(b));
}
__device__ __forceinline__ void upk2(u64 v, float& lo, float& hi) {
    asm("mov.b64 {%0,%1}, %2;" : "=f"(lo), "=f"(hi) : "l"(v));
}

#if HAS_TCGEN05
// ---------------- sm_103a-only helpers ----------------
__device__ __forceinline__ uint32_t smem_u32(const void* p) {
    uint32_t a;
    asm("{ .reg .u64 t; cvta.to.shared.u64 t, %1; cvt.u32.u64 %0, t; }" : "=r"(a) : "l"(p));
    return a;
}
__device__ __forceinline__ uint32_t elect1() {
    uint32_t p;
    asm volatile("{ .reg .pred p; elect.sync _|p, 0xFFFFFFFF; selp.b32 %0,1,0,p; }" : "=r"(p));
    return p;
}
#define SWZ(o) ((o) ^ ((((uint32_t)(o)) >> 3) & 0x70))

static __device__ __forceinline__ uint64_t mkdesc(uint32_t addr) {
    const uint64_t base = (uint64_t(2) << 61) | (uint64_t(1) << 46)
                        | (uint64_t(64) << 32) | (uint64_t(1) << 16);  // SW128
    return base | ((uint64_t)(addr >> 4) & 0x3FFF);
}
__device__ __forceinline__ void tmem_alloc(uint32_t smem_addr, uint32_t ncols) {
    asm volatile("tcgen05.alloc.cta_group::1.sync.aligned.shared::cta.b32 [%0], %1;"
                 :: "r"(smem_addr), "r"(ncols) : "memory");
}
__device__ __forceinline__ void tmem_relinq() {
    asm volatile("tcgen05.relinquish_alloc_permit.cta_group::1.sync.aligned;");
}
__device__ __forceinline__ void tmem_dealloc(uint32_t tmem, uint32_t ncols) {
    asm volatile("tcgen05.dealloc.cta_group::1.sync.aligned.b32 %0, %1;" :: "r"(tmem), "r"(ncols));
}
__device__ __forceinline__ void mbar_init(uint32_t a, uint32_t cnt) {
    asm volatile("mbarrier.init.shared.b64 [%0], %1;" :: "r"(a), "r"(cnt) : "memory");
}
__device__ __forceinline__ void mbar_inval(uint32_t a) {
    asm volatile("mbarrier.inval.shared.b64 [%0];" :: "r"(a) : "memory");
}
__device__ __forceinline__ void mbar_wait(uint32_t a, uint32_t par) {
    uint32_t done;
    asm volatile("{ .reg .pred p; mbarrier.try_wait.parity.acquire.cta.shared::cta.b64 p, [%1], %2;"
                 " selp.b32 %0,1,0,p; }" : "=r"(done) : "r"(a), "r"(par) : "memory");
    if (!done) {
        asm volatile("{ .reg .pred P1; WL_%=: mbarrier.try_wait.parity.acquire.cta.shared::cta.b64 P1, [%0], %1, 0x989680;"
                     " @P1 bra.uni WD_%=; bra.uni WL_%=; WD_%=: }" :: "r"(a), "r"(par) : "memory");
    }
}
__device__ __forceinline__ void mma_commit(uint32_t mbar) {
    asm volatile("tcgen05.commit.cta_group::1.mbarrier::arrive::one.shared::cluster.b64 [%0];"
                 :: "r"(mbar) : "memory");
}
// TS form bf16: A in TMEM, B via SMEM descriptor
__device__ __forceinline__ void mma_bf16_ts(uint32_t d, uint32_t a, uint64_t bd, uint32_t en) {
    asm volatile("{ .reg .pred p; setp.ne.u32 p, %4, 0;"
                 " tcgen05.mma.cta_group::1.kind::f16 [%0], [%1], %2, %3, {%5,%5,%5,%5}, p; }"
                 :: "r"(d), "r"(a), "l"(bd), "r"(IDESC_BF16), "r"(en), "r"(0u) : "memory");
}
__device__ __forceinline__ void fence_async_shared() {
    asm volatile("fence.proxy.async.shared::cta;" ::: "memory");
}
__device__ __forceinline__ void tc_fence_before() {
    asm volatile("tcgen05.fence::before_thread_sync;" ::: "memory");
}
__device__ __forceinline__ void tc_fence_after() {
    asm volatile("tcgen05.fence::after_thread_sync;" ::: "memory");
}
__device__ __forceinline__ void tc_wait_st() {
    asm volatile("tcgen05.wait::st.sync.aligned;" ::: "memory");
}
__device__ __forceinline__ void tc_wait_ld() {
    asm volatile("tcgen05.wait::ld.sync.aligned;" ::: "memory");
}
__device__ __forceinline__ void sttm_x16(uint32_t a, const uint32_t* r) {
    asm volatile("tcgen05.st.sync.aligned.32x32b.x16.b32 [%0], "
        "{%1,%2,%3,%4,%5,%6,%7,%8,%9,%10,%11,%12,%13,%14,%15,%16};"
        :: "r"(a),
           "r"(r[0]),"r"(r[1]),"r"(r[2]),"r"(r[3]),"r"(r[4]),"r"(r[5]),"r"(r[6]),"r"(r[7]),
           "r"(r[8]),"r"(r[9]),"r"(r[10]),"r"(r[11]),"r"(r[12]),"r"(r[13]),"r"(r[14]),"r"(r[15])
        : "memory");
}
__device__ __forceinline__ void ldtm_x32(uint32_t* r, uint32_t a) {
    asm volatile("tcgen05.ld.sync.aligned.32x32b.x32.b32 "
        "{%0,%1,%2,%3,%4,%5,%6,%7,%8,%9,%10,%11,%12,%13,%14,%15,"
        "%16,%17,%18,%19,%20,%21,%22,%23,%24,%25,%26,%27,%28,%29,%30,%31}, [%32];"
        : "=r"(r[0]),"=r"(r[1]),"=r"(r[2]),"=r"(r[3]),"=r"(r[4]),"=r"(r[5]),"=r"(r[6]),"=r"(r[7]),
          "=r"(r[8]),"=r"(r[9]),"=r"(r[10]),"=r"(r[11]),"=r"(r[12]),"=r"(r[13]),"=r"(r[14]),"=r"(r[15]),
          "=r"(r[16]),"=r"(r[17]),"=r"(r[18]),"=r"(r[19]),"=r"(r[20]),"=r"(r[21]),"=r"(r[22]),"=r"(r[23]),
          "=r"(r[24]),"=r"(r[25]),"=r"(r[26]),"=r"(r[27]),"=r"(r[28]),"=r"(r[29]),"=r"(r[30]),"=r"(r[31])
        : "r"(a));
}
__device__ __forceinline__ void ldtm_x16(uint32_t* r, uint32_t a) {
    asm volatile("tcgen05.ld.sync.aligned.32x32b.x16.b32 "
        "{%0,%1,%2,%3,%4,%5,%6,%7,%8,%9,%10,%11,%12,%13,%14,%15}, [%16];"
        : "=r"(r[0]),"=r"(r[1]),"=r"(r[2]),"=r"(r[3]),"=r"(r[4]),"=r"(r[5]),"=r"(r[6]),"=r"(r[7]),
          "=r"(r[8]),"=r"(r[9]),"=r"(r[10]),"=r"(r[11]),"=r"(r[12]),"=r"(r[13]),"=r"(r[14]),"=r"(r[15])
        : "r"(a));
}

__device__ __forceinline__ uint16_t bf16b(float v) {
    return __bfloat16_as_ushort(__float2bfloat16_rn(v));
}

// Build one bf16 im2col A-chunk for input row ci directly into TMEM (warps 0-3).
// Chunk: 128 px rows x 16 cols; cols 0-7 = hi(dx pairs), cols 8-15 = lo(dx pairs).
// Each 32-bit col packs K elements (2j, 2j+1): even element in low half.
__device__ __forceinline__ void build_chunk_tmem(const float* __restrict__ xs,
                                                 uint32_t tmem_a, int ci, int wid, int lid) {
    const float* xr = xs + ci * HW;
    const int xpos = (wid << 5) + lid;
    uint32_t regs[16];
#pragma unroll
    for (int j = 0; j < 8; ++j) {
        int dx0 = 2 * j, dx1 = 2 * j + 1;
        int s0 = xpos + dx0 - 7, s1 = xpos + dx1 - 7;
        float v0 = (s0 >= 0 && s0 < HW) ? xr[s0] : 0.f;
        float v1 = (dx1 < 15 && s1 >= 0 && s1 < HW) ? xr[s1] : 0.f;
        uint16_t h0 = bf16b(v0), h1 = bf16b(v1);
        float r0 = v0 - __bfloat162float(__ushort_as_bfloat16(h0));
        float r1 = v1 - __bfloat162float(__ushort_as_bfloat16(h1));
        regs[j]     = (uint32_t)h0 | ((uint32_t)h1 << 16);
        regs[8 + j] = (uint32_t)bf16b(r0) | ((uint32_t)bf16b(r1) << 16);
    }
    sttm_x16(tmem_a + ((uint32_t)wid << 21), regs);
}
// Filters for one dy into SMEM (SW128, bf16): 48 rows x 64 bf16 (128B rows).
// cols 0-15 = hi (dx 0-14 + pad0), cols 16-31 = lo, cols 32-63 = 0. Threads 128-255.
__device__ __forceinline__ void build_filt(char* smem, int boff, const float* __restrict__ filters,
                                           int dy, int t) {
    for (int i = t; i < NF * 64; i += 128) {
        int f = i >> 6, col = i & 63;
        uint16_t val = 0;
        if (col < 32) {
            int dx = col & 15;
            if (dx < 15) {
                float w = filters[(f >> 1) * 450 + (f & 1) * 225 + dy * 15 + dx];
                uint16_t h = bf16b(w);
                if (col < 16) val = h;
                else val = bf16b(w - __bfloat162float(__ushort_as_bfloat16(h)));
            }
        }
        *(uint16_t*)(smem + boff + SWZ(f * 128 + col * 2)) = val;
    }
}
#endif  // HAS_TCGEN05

// ---------------------------------------------------------------------------
// Kernel A: Gabor conv + magnitude.
// sm_103a: tcgen05 bf16 TS-mode implicit GEMM (A im2col in TMEM, 3xBF16 split).
// grid (32 row-groups, 128 planes), 256 threads
// ---------------------------------------------------------------------------
__global__ __launch_bounds__(256, 2)
void gabor_mma_kernel(const float* __restrict__ x, const float* __restrict__ filters) {
#if HAS_TCGEN05
    extern __shared__ char smem[];
    const uint32_t sb = smem_u32(smem);
    const int tid = threadIdx.x, wid = tid >> 5, lid = tid & 31;
    const int plane = blockIdx.y;
    const int y0 = blockIdx.x * RT;
    const int b = plane >> 5, c = plane & 31;

    if (wid == 0) tmem_alloc(sb + SM_TMEM, 512);
    if (tid == 0)
        for (int i = 0; i < KK; ++i) mbar_init(sb + SM_MBAR + i * 8, 1);

    // stage NCHUNK x-rows (zero-padded in y)
    const float* xp = x + (size_t)plane * PLANE;
    float* xs = (float*)(smem + SM_X);
    for (int i = tid; i < NCHUNK * HW; i += 256) {
        int rr = i >> 7, cc = i & 127;
        int gy = y0 + rr - 7;
        xs[i] = (gy >= 0 && gy < HW) ? xp[gy * HW + cc] : 0.f;
    }
    __syncthreads();
    uint32_t tmem;
    asm volatile("ld.shared.b32 %0, [%1];" : "=r"(tmem) : "r"(sb + SM_TMEM));
    if (wid == 0) tmem_relinq();

    // prebuild A chunks 0..2 into TMEM ring slots 0..2
    if (wid < 4) {
        for (int ci = 0; ci < RT - 1; ++ci)
            build_chunk_tmem(xs, tmem + TM_A0 + ci * 16, ci, wid, lid);
        tc_wait_st();
    }

    for (int dy = 0; dy < KK; ++dy) {
        // pipeline depth 4: B slot (dy&3) reuse + A slot ((dy+3)%8) reuse both safe
        if (dy >= 4) mbar_wait(sb + SM_MBAR + (dy - 4) * 8, 0);
        if (wid < 4) {
            build_chunk_tmem(xs, tmem + TM_A0 + ((dy + 3) % ARING) * 16, dy + 3, wid, lid);
            tc_wait_st();
        } else {
            build_filt(smem, SM_B + (dy & 3) * SLOT_BF, filters, dy, tid - 128);
        }
        tc_fence_before();
        fence_async_shared();
        __syncthreads();
        if (wid == 0) {
            tc_fence_after();
            if (elect1()) {
                uint64_t bd = mkdesc(sb + SM_B + (dy & 3) * SLOT_BF);
#pragma unroll
                for (int r = 0; r < RT; ++r) {
                    uint32_t a = tmem + TM_A0 + ((dy + r) % ARING) * 16;
                    uint32_t d = tmem + r * 64;
                    mma_bf16_ts(d, a + 0, bd + 0, dy > 0);  // hi x hi (K=16)
                    mma_bf16_ts(d, a + 8, bd + 0, 1);       // lo x hi
                    mma_bf16_ts(d, a + 0, bd + 2, 1);       // hi x lo
                }
                mma_commit(sb + SM_MBAR + dy * 8);
            }
        }
    }
    mbar_wait(sb + SM_MBAR + (KK - 1) * 8, 0);
    tc_fence_after();

    // epilogue: warps 0-3 -> tiles 0,1 ; warps 4-7 -> tiles 2,3 ; sub = wid&3
    const int sub = wid & 3;
    const int xc = sub * 32 + lid;
    const size_t mbase = ((size_t)b * CIN + (size_t)c * NSO) * PLANE + xc;
#pragma unroll
    for (int rr = 0; rr < 2; ++rr) {
        const int r = (wid >> 2) * 2 + rr;
        uint32_t rg[48];
        ldtm_x32(rg, tmem + r * 64);
        ldtm_x16(rg + 32, tmem + r * 64 + 32);
        tc_wait_ld();
        const int y = y0 + r;
#pragma unroll
        for (int s = 0; s < NSO; ++s) {
            float re = __uint_as_float(rg[2 * s]);
            float im = __uint_as_float(rg[2 * s + 1]);
            g_mag[mbase + (size_t)s * PLANE + (size_t)y * HW] = sqrtf(re * re + im * im);
        }
    }
    __syncthreads();
    if (tid == 0)
        for (int i = 0; i < KK; ++i) mbar_inval(sb + SM_MBAR + i * 8);
    __syncthreads();
    if (wid == 0) tmem_dealloc(tmem, 512);

#else  // ---------------- scalar FFMA2 fallback (non-arch-specific pass) -----
    extern __shared__ float smf[];
    float* fs = smf;                        // [225][48]
    float* xs = smf + 225 * NF;             // [18][144]
    const int XW = 144;
    const int tid = threadIdx.x;
    const int plane = blockIdx.y;
    const int y0 = blockIdx.x * RT;
    const int b = plane >> 5, c = plane & 31;

    for (int i = tid; i < 225 * NF; i += 256) {
        int tap = i / NF, f = i - tap * NF;
        fs[i] = filters[(f >> 1) * 450 + (f & 1) * 225 + tap];
    }
    const float* xp = x + (size_t)plane * PLANE;
    for (int i = tid; i < NCHUNK * XW; i += 256) {
        int rr = i / XW, cc = i - rr * XW;
        int gy = y0 + rr - 7, gx = cc - 7;
        xs[i] = (gy >= 0 && gy < HW && gx >= 0 && gx < HW) ? xp[gy * HW + gx] : 0.f;
    }
    __syncthreads();

    const int x0 = (tid & 63) * 2;
    const int ry = tid >> 6;
    const size_t mbase0 = ((size_t)b * CIN + (size_t)c * NSO) * PLANE
                        + (size_t)(y0 + ry) * HW + x0;
    for (int g = 0; g < 4; ++g) {
        u64 acc[2][6];
#pragma unroll
        for (int p = 0; p < 2; ++p)
#pragma unroll
            for (int s = 0; s < 6; ++s) acc[p][s] = 0ull;
        for (int dy = 0; dy < KK; ++dy) {
            const float* xr = xs + (ry + dy) * XW + x0;
            const float* wr = fs + dy * KK * NF + g * 12;
#pragma unroll
            for (int dx = 0; dx < KK; ++dx) {
                const float* w = wr + dx * NF;
                ulonglong2 wa = *(const ulonglong2*)(w);
                ulonglong2 wb = *(const ulonglong2*)(w + 4);
                ulonglong2 wc = *(const ulonglong2*)(w + 8);
                u64 wp[6] = {wa.x, wa.y, wb.x, wb.y, wc.x, wc.y};
                u64 xv[2] = {splat(xr[dx]), splat(xr[dx + 1])};
#pragma unroll
                for (int p = 0; p < 2; ++p)
#pragma unroll
                    for (int s = 0; s < 6; ++s) fma2(acc[p][s], xv[p], wp[s]);
            }
        }
#pragma unroll
        for (int s = 0; s < 6; ++s) {
            float re0, im0, re1, im1;
            upk2(acc[0][s], re0, im0);
            upk2(acc[1][s], re1, im1);
            float2 m = make_float2(sqrtf(re0*re0 + im0*im0), sqrtf(re1*re1 + im1*im1));
            *(float2*)(g_mag + mbase0 + (size_t)(g * 6 + s) * PLANE) = m;
        }
    }
#endif
}

// ---------------------------------------------------------------------------
// Kernel B: channel mix (FFMA2), bias dropped (cancels in instance norm)
// ---------------------------------------------------------------------------
static const int SMEM_MIX = CIN * 32 * 4;

__global__ __launch_bounds__(256, 2)
void mix_kernel(const float* __restrict__ w1) {
    extern __shared__ float w1s[];
    const int tid = threadIdx.x;
    for (int i = tid; i < CIN * 32; i += 256) {
        int j = i >> 5, o = i & 31;
        w1s[i] = w1[o * CIN + j];
    }
    __syncthreads();

    const int bb = blockIdx.y;
    const int q0 = blockIdx.x * 512 + tid * 2;
    const float* mp = g_mag + (size_t)bb * CIN * PLANE + q0;

    u64 acc[16][2];
#pragma unroll
    for (int op = 0; op < 16; ++op) { acc[op][0] = 0ull; acc[op][1] = 0ull; }

#pragma unroll 4
    for (int j = 0; j < CIN; ++j) {
        float2 m = *(const float2*)(mp + (size_t)j * PLANE);
        u64 mx = splat(m.x), my = splat(m.y);
        const ulonglong2* wrow = (const ulonglong2*)(w1s + j * 32);
#pragma unroll
        for (int q4 = 0; q4 < 8; ++q4) {
            ulonglong2 w2 = wrow[q4];
            fma2(acc[q4 * 2 + 0][0], mx, w2.x);
            fma2(acc[q4 * 2 + 0][1], my, w2.x);
            fma2(acc[q4 * 2 + 1][0], mx, w2.y);
            fma2(acc[q4 * 2 + 1][1], my, w2.y);
        }
    }
#pragma unroll
    for (int op = 0; op < 16; ++op) {
        float a0lo, a0hi, a1lo, a1hi;
        upk2(acc[op][0], a0lo, a0hi);
        upk2(acc[op][1], a1lo, a1hi);
        *(float2*)(g_z + (size_t)(bb * 32 + 2 * op)     * PLANE + q0) = make_float2(a0lo, a1lo);
        *(float2*)(g_z + (size_t)(bb * 32 + 2 * op + 1) * PLANE + q0) = make_float2(a0hi, a1hi);
    }
}

// ---------------------------------------------------------------------------
__global__ void stats_kernel() {
    const int plane = blockIdx.x;
    const float* zp = g_z + (size_t)plane * PLANE;
    const int tid = threadIdx.x;
    float s = 0.f, s2 = 0.f;
    for (int i = tid * 4; i < PLANE; i += 1024) {
        float4 v = *(const float4*)(zp + i);
        s  += v.x + v.y + v.z + v.w;
        s2 += v.x * v.x + v.y * v.y + v.z * v.z + v.w * v.w;
    }
    __shared__ float r1[256], r2[256];
    r1[tid] = s; r2[tid] = s2;
    __syncthreads();
    for (int st = 128; st > 0; st >>= 1) {
        if (tid < st) { r1[tid] += r1[tid + st]; r2[tid] += r2[tid + st]; }
        __syncthreads();
    }
    if (tid == 0) {
        float mean = r1[0] * (1.f / PLANE);
        float var  = r2[0] * (1.f / PLANE) - mean * mean;
        g_stats[plane * 2]     = mean;
        g_stats[plane * 2 + 1] = rsqrtf(var + 1e-5f);
    }
}

__global__ void norm_kernel(float* __restrict__ out) {
    __shared__ float s[32][33];
    const int plane = blockIdx.y;
    const int tile  = blockIdx.x;
    const int hb = (tile >> 2) * 32, wb = (tile & 3) * 32;
    const float mean = g_stats[plane * 2];
    const float rstd = g_stats[plane * 2 + 1];
    const float* zp = g_z + (size_t)plane * PLANE;
    float* op = out + (size_t)plane * PLANE;
    const int cc = threadIdx.x & 31;
    const int r0 = threadIdx.x >> 5;
#pragma unroll
    for (int k = 0; k < 4; ++k) {
        int rr = r0 + k * 8;
        s[rr][cc] = zp[(wb + rr) * HW + hb + cc];
    }
    __syncthreads();
#pragma unroll
    for (int k = 0; k < 4; ++k) {
        int rr = r0 + k * 8;
        op[(hb + rr) * HW + wb + cc] = (s[cc][rr] - mean) * rstd;
    }
}

// ---------------------------------------------------------------------------
extern "C" void kernel_launch(void* const* d_in, const int* in_sizes, int n_in,
                              void* d_out, int out_size) {
    const float* x       = (const float*)d_in[0];
    const float* filters = (const float*)d_in[1];
    const float* w1      = (const float*)d_in[2];
    float* out = (float*)d_out;

    cudaFuncSetAttribute(gabor_mma_kernel, cudaFuncAttributeMaxDynamicSharedMemorySize, SMEM_GABOR);
    cudaFuncSetAttribute(mix_kernel,       cudaFuncAttributeMaxDynamicSharedMemorySize, SMEM_MIX);

    gabor_mma_kernel<<<dim3(32, 128), 256, SMEM_GABOR>>>(x, filters);
    mix_kernel<<<dim3(32, 4), 256, SMEM_MIX>>>(w1);
    stats_kernel<<<128, 256>>>();
    norm_kernel<<<dim3(16, 128), 256>>>(out);
}

// round 7
// speedup vs baseline: 1.0002x; 1.0002x over previous
#include <cuda_runtime.h>
#include <cuda_bf16.h>
#include <cstdint>
#include <math.h>

#define KK     15
#define HW     128
#define PLANE  16384
#define CIN    768
#define NSO    24
#define NF     48          // filters (N dim)
#define RT     4           // output rows per CTA
#define ARING  8           // TMEM A-chunk ring slots (16 cols each)
#define NCHUNK 18          // RT + 14 input rows per CTA

// ---- smem layout (bytes) for tcgen05 path ----
#define SM_TMEM   0
#define SM_MBAR   64                 // 15 mbarriers x 8B
#define SM_B      1024               // 4 B-slots x 6144B (48 rows x 128B, SW128)
#define SLOT_BF   6144
#define SM_X      (SM_B + 4*SLOT_BF) // 25600: 18 x-rows x 128 floats
// tcgen05 path needs ~34816; fallback needs 53568. Launch with max.
#define SMEM_GABOR 53568

// TMEM columns: D tiles at r*64 (r=0..3); A ring at 256 + slot*16 (slots 0..7)
#define TM_A0  256

// idesc kind::f16 bf16: dfmt=F32(1)<<4 | atype=BF16(1)<<7 | btype=BF16(1)<<10
//                        | (N/8)<<17 | (M/16)<<24
#define IDESC_BF16 ((1u<<4) | (1u<<7) | (1u<<10) | ((NF/8)<<17) | ((128/16)<<24))

#if defined(__CUDA_ARCH__) && (defined(__CUDA_ARCH_FEAT_SM103_ALL) || defined(__CUDA_ARCH_SPECIFIC__))
#define HAS_TCGEN05 1
#else
#define HAS_TCGEN05 0
#endif

typedef unsigned long long u64;

// Scratch (.bss)
__device__ float g_mag[(size_t)4 * CIN * PLANE];   // [b][c*24+so][y*128+x]
__device__ float g_z[(size_t)128 * PLANE];
__device__ float g_stats[256];

// ---------------- portable helpers ----------------
__device__ __forceinline__ u64 splat(float v) {
    u64 r; asm("mov.b64 %0, {%1,%1};" : "=l"(r) : "f"(v)); return r;
}
__device__ __forceinline__ void fma2(u64& d, u64 a, u64 b) {
    asm("fma.rn.f32x2 %0, %1, %2, %0;" : "+l"(d) : "l"(a), "l"(b));
}
__device__ __forceinline__ void upk2(u64 v, float& lo, float& hi) {
    asm("mov.b64 {%0,%1}, %2;" : "=f"(lo), "=f"(hi) : "l"(v));
}

#if HAS_TCGEN05
// ---------------- sm_103a-only helpers ----------------
__device__ __forceinline__ uint32_t smem_u32(const void* p) {
    uint32_t a;
    asm("{ .reg .u64 t; cvta.to.shared.u64 t, %1; cvt.u32.u64 %0, t; }" : "=r"(a) : "l"(p));
    return a;
}
__device__ __forceinline__ uint32_t elect1() {
    uint32_t p;
    asm volatile("{ .reg .pred p; elect.sync _|p, 0xFFFFFFFF; selp.b32 %0,1,0,p; }" : "=r"(p));
    return p;
}
#define SWZ(o) ((o) ^ ((((uint32_t)(o)) >> 3) & 0x70))

static __device__ __forceinline__ uint64_t mkdesc(uint32_t addr) {
    const uint64_t base = (uint64_t(2) << 61) | (uint64_t(1) << 46)
                        | (uint64_t(64) << 32) | (uint64_t(1) << 16);  // SW128
    return base | ((uint64_t)(addr >> 4) & 0x3FFF);
}
__device__ __forceinline__ void tmem_alloc(uint32_t smem_addr, uint32_t ncols) {
    asm volatile("tcgen05.alloc.cta_group::1.sync.aligned.shared::cta.b32 [%0], %1;"
                 :: "r"(smem_addr), "r"(ncols) : "memory");
}
__device__ __forceinline__ void tmem_relinq() {
    asm volatile("tcgen05.relinquish_alloc_permit.cta_group::1.sync.aligned;");
}
__device__ __forceinline__ void tmem_dealloc(uint32_t tmem, uint32_t ncols) {
    asm volatile("tcgen05.dealloc.cta_group::1.sync.aligned.b32 %0, %1;" :: "r"(tmem), "r"(ncols));
}
__device__ __forceinline__ void mbar_init(uint32_t a, uint32_t cnt) {
    asm volatile("mbarrier.init.shared.b64 [%0], %1;" :: "r"(a), "r"(cnt) : "memory");
}
__device__ __forceinline__ void mbar_inval(uint32_t a) {
    asm volatile("mbarrier.inval.shared.b64 [%0];" :: "r"(a) : "memory");
}
__device__ __forceinline__ void mbar_wait(uint32_t a, uint32_t par) {
    uint32_t done;
    asm volatile("{ .reg .pred p; mbarrier.try_wait.parity.acquire.cta.shared::cta.b64 p, [%1], %2;"
                 " selp.b32 %0,1,0,p; }" : "=r"(done) : "r"(a), "r"(par) : "memory");
    if (!done) {
        asm volatile("{ .reg .pred P1; WL_%=: mbarrier.try_wait.parity.acquire.cta.shared::cta.b64 P1, [%0], %1, 0x989680;"
                     " @P1 bra.uni WD_%=; bra.uni WL_%=; WD_%=: }" :: "r"(a), "r"(par) : "memory");
    }
}
__device__ __forceinline__ void mma_commit(uint32_t mbar) {
    asm volatile("tcgen05.commit.cta_group::1.mbarrier::arrive::one.shared::cluster.b64 [%0];"
                 :: "r"(mbar) : "memory");
}
// TS form bf16: A in TMEM, B via SMEM descriptor
__device__ __forceinline__ void mma_bf16_ts(uint32_t d, uint32_t a, uint64_t bd, uint32_t en) {
    asm volatile("{ .reg .pred p; setp.ne.u32 p, %4, 0;"
                 " tcgen05.mma.cta_group::1.kind::f16 [%0], [%1], %2, %3, {%5,%5,%5,%5}, p; }"
                 :: "r"(d), "r"(a), "l"(bd), "r"(IDESC_BF16), "r"(en), "r"(0u) : "memory");
}
__device__ __forceinline__ void fence_async_shared() {
    asm volatile("fence.proxy.async.shared::cta;" ::: "memory");
}
__device__ __forceinline__ void tc_fence_before() {
    asm volatile("tcgen05.fence::before_thread_sync;" ::: "memory");
}
__device__ __forceinline__ void tc_fence_after() {
    asm volatile("tcgen05.fence::after_thread_sync;" ::: "memory");
}
__device__ __forceinline__ void tc_wait_st() {
    asm volatile("tcgen05.wait::st.sync.aligned;" ::: "memory");
}
__device__ __forceinline__ void tc_wait_ld() {
    asm volatile("tcgen05.wait::ld.sync.aligned;" ::: "memory");
}
__device__ __forceinline__ void sttm_x16(uint32_t a, const uint32_t* r) {
    asm volatile("tcgen05.st.sync.aligned.32x32b.x16.b32 [%0], "
        "{%1,%2,%3,%4,%5,%6,%7,%8,%9,%10,%11,%12,%13,%14,%15,%16};"
        :: "r"(a),
           "r"(r[0]),"r"(r[1]),"r"(r[2]),"r"(r[3]),"r"(r[4]),"r"(r[5]),"r"(r[6]),"r"(r[7]),
           "r"(r[8]),"r"(r[9]),"r"(r[10]),"r"(r[11]),"r"(r[12]),"r"(r[13]),"r"(r[14]),"r"(r[15])
        : "memory");
}
__device__ __forceinline__ void ldtm_x32(uint32_t* r, uint32_t a) {
    asm volatile("tcgen05.ld.sync.aligned.32x32b.x32.b32 "
        "{%0,%1,%2,%3,%4,%5,%6,%7,%8,%9,%10,%11,%12,%13,%14,%15,"
        "%16,%17,%18,%19,%20,%21,%22,%23,%24,%25,%26,%27,%28,%29,%30,%31}, [%32];"
        : "=r"(r[0]),"=r"(r[1]),"=r"(r[2]),"=r"(r[3]),"=r"(r[4]),"=r"(r[5]),"=r"(r[6]),"=r"(r[7]),
          "=r"(r[8]),"=r"(r[9]),"=r"(r[10]),"=r"(r[11]),"=r"(r[12]),"=r"(r[13]),"=r"(r[14]),"=r"(r[15]),
          "=r"(r[16]),"=r"(r[17]),"=r"(r[18]),"=r"(r[19]),"=r"(r[20]),"=r"(r[21]),"=r"(r[22]),"=r"(r[23]),
          "=r"(r[24]),"=r"(r[25]),"=r"(r[26]),"=r"(r[27]),"=r"(r[28]),"=r"(r[29]),"=r"(r[30]),"=r"(r[31])
        : "r"(a));
}
__device__ __forceinline__ void ldtm_x16(uint32_t* r, uint32_t a) {
    asm volatile("tcgen05.ld.sync.aligned.32x32b.x16.b32 "
        "{%0,%1,%2,%3,%4,%5,%6,%7,%8,%9,%10,%11,%12,%13,%14,%15}, [%16];"
        : "=r"(r[0]),"=r"(r[1]),"=r"(r[2]),"=r"(r[3]),"=r"(r[4]),"=r"(r[5]),"=r"(r[6]),"=r"(r[7]),
          "=r"(r[8]),"=r"(r[9]),"=r"(r[10]),"=r"(r[11]),"=r"(r[12]),"=r"(r[13]),"=r"(r[14]),"=r"(r[15])
        : "r"(a));
}

__device__ __forceinline__ uint16_t bf16b(float v) {
    return __bfloat16_as_ushort(__float2bfloat16_rn(v));
}

// Build one bf16 im2col A-chunk for input row ci directly into TMEM (warps 0-3).
// Chunk: 128 px rows x 16 cols; cols 0-7 = hi(dx pairs), cols 8-15 = lo(dx pairs).
__device__ __forceinline__ void build_chunk_tmem(const float* __restrict__ xs,
                                                 uint32_t tmem_a, int ci, int wid, int lid) {
    const float* xr = xs + ci * HW;
    const int xpos = (wid << 5) + lid;
    uint32_t regs[16];
#pragma unroll
    for (int j = 0; j < 8; ++j) {
        int dx0 = 2 * j, dx1 = 2 * j + 1;
        int s0 = xpos + dx0 - 7, s1 = xpos + dx1 - 7;
        float v0 = (s0 >= 0 && s0 < HW) ? xr[s0] : 0.f;
        float v1 = (dx1 < 15 && s1 >= 0 && s1 < HW) ? xr[s1] : 0.f;
        uint16_t h0 = bf16b(v0), h1 = bf16b(v1);
        float r0 = v0 - __bfloat162float(__ushort_as_bfloat16(h0));
        float r1 = v1 - __bfloat162float(__ushort_as_bfloat16(h1));
        regs[j]     = (uint32_t)h0 | ((uint32_t)h1 << 16);
        regs[8 + j] = (uint32_t)bf16b(r0) | ((uint32_t)bf16b(r1) << 16);
    }
    sttm_x16(tmem_a + ((uint32_t)wid << 21), regs);
}
// Filters for one dy into SMEM (SW128, bf16): 48 rows x 64 bf16 (128B rows).
__device__ __forceinline__ void build_filt(char* smem, int boff, const float* __restrict__ filters,
                                           int dy, int t) {
    for (int i = t; i < NF * 64; i += 128) {
        int f = i >> 6, col = i & 63;
        uint16_t val = 0;
        if (col < 32) {
            int dx = col & 15;
            if (dx < 15) {
                float w = filters[(f >> 1) * 450 + (f & 1) * 225 + dy * 15 + dx];
                uint16_t h = bf16b(w);
                if (col < 16) val = h;
                else val = bf16b(w - __bfloat162float(__ushort_as_bfloat16(h)));
            }
        }
        *(uint16_t*)(smem + boff + SWZ(f * 128 + col * 2)) = val;
    }
}
#endif  // HAS_TCGEN05

// ---------------------------------------------------------------------------
// Kernel A: Gabor conv + magnitude.
// sm_103a: tcgen05 bf16 TS-mode implicit GEMM (A im2col in TMEM, 3xBF16 split).
// grid (32 row-groups, 128 planes), 256 threads, occupancy 1 (full-TMEM CTA)
// ---------------------------------------------------------------------------
__global__ __launch_bounds__(256, 1)
void gabor_mma_kernel(const float* __restrict__ x, const float* __restrict__ filters) {
#if HAS_TCGEN05
    extern __shared__ char smem[];
    const uint32_t sb = smem_u32(smem);
    const int tid = threadIdx.x, wid = tid >> 5, lid = tid & 31;
    const int plane = blockIdx.y;
    const int y0 = blockIdx.x * RT;
    const int b = plane >> 5, c = plane & 31;

    if (wid == 0) tmem_alloc(sb + SM_TMEM, 512);
    if (tid == 0)
        for (int i = 0; i < KK; ++i) mbar_init(sb + SM_MBAR + i * 8, 1);

    // stage NCHUNK x-rows (zero-padded in y)
    const float* xp = x + (size_t)plane * PLANE;
    float* xs = (float*)(smem + SM_X);
    for (int i = tid; i < NCHUNK * HW; i += 256) {
        int rr = i >> 7, cc = i & 127;
        int gy = y0 + rr - 7;
        xs[i] = (gy >= 0 && gy < HW) ? xp[gy * HW + cc] : 0.f;
    }
    __syncthreads();
    uint32_t tmem;
    asm volatile("ld.shared.b32 %0, [%1];" : "=r"(tmem) : "r"(sb + SM_TMEM));
    if (wid == 0) tmem_relinq();

    // prebuild A chunks 0..2 into TMEM ring slots 0..2
    if (wid < 4) {
        for (int ci = 0; ci < RT - 1; ++ci)
            build_chunk_tmem(xs, tmem + TM_A0 + ci * 16, ci, wid, lid);
        tc_wait_st();
    }

    for (int dy = 0; dy < KK; ++dy) {
        // pipeline depth 4: B slot (dy&3) reuse + A slot ((dy+3)%8) reuse both safe
        if (dy >= 4) mbar_wait(sb + SM_MBAR + (dy - 4) * 8, 0);
        if (wid < 4) {
            build_chunk_tmem(xs, tmem + TM_A0 + ((dy + 3) % ARING) * 16, dy + 3, wid, lid);
            tc_wait_st();
        } else {
            build_filt(smem, SM_B + (dy & 3) * SLOT_BF, filters, dy, tid - 128);
        }
        tc_fence_before();
        fence_async_shared();
        __syncthreads();
        if (wid == 0) {
            tc_fence_after();
            if (elect1()) {
                uint64_t bd = mkdesc(sb + SM_B + (dy & 3) * SLOT_BF);
#pragma unroll
                for (int r = 0; r < RT; ++r) {
                    uint32_t a = tmem + TM_A0 + ((dy + r) % ARING) * 16;
                    uint32_t d = tmem + r * 64;
                    mma_bf16_ts(d, a + 0, bd + 0, dy > 0);  // hi x hi (K=16)
                    mma_bf16_ts(d, a + 8, bd + 0, 1);       // lo x hi
                    mma_bf16_ts(d, a + 0, bd + 2, 1);       // hi x lo
                }
                mma_commit(sb + SM_MBAR + dy * 8);
            }
        }
    }
    mbar_wait(sb + SM_MBAR + (KK - 1) * 8, 0);
    tc_fence_after();

    // epilogue: warps 0-3 -> tiles 0,1 ; warps 4-7 -> tiles 2,3 ; sub = wid&3
    const int sub = wid & 3;
    const int xc = sub * 32 + lid;
    const size_t mbase = ((size_t)b * CIN + (size_t)c * NSO) * PLANE + xc;
#pragma unroll
    for (int rr = 0; rr < 2; ++rr) {
        const int r = (wid >> 2) * 2 + rr;
        uint32_t rg[48];
        ldtm_x32(rg, tmem + r * 64);
        ldtm_x16(rg + 32, tmem + r * 64 + 32);
        tc_wait_ld();
        const int y = y0 + r;
#pragma unroll
        for (int s = 0; s < NSO; ++s) {
            float re = __uint_as_float(rg[2 * s]);
            float im = __uint_as_float(rg[2 * s + 1]);
            g_mag[mbase + (size_t)s * PLANE + (size_t)y * HW] = sqrtf(re * re + im * im);
        }
    }
    __syncthreads();
    if (tid == 0)
        for (int i = 0; i < KK; ++i) mbar_inval(sb + SM_MBAR + i * 8);
    __syncthreads();
    if (wid == 0) tmem_dealloc(tmem, 512);

#else  // ---------------- scalar FFMA2 fallback (non-arch-specific pass) -----
    extern __shared__ float smf[];
    float* fs = smf;                        // [225][48]
    float* xs = smf + 225 * NF;             // [18][144]
    const int XW = 144;
    const int tid = threadIdx.x;
    const int plane = blockIdx.y;
    const int y0 = blockIdx.x * RT;
    const int b = plane >> 5, c = plane & 31;

    for (int i = tid; i < 225 * NF; i += 256) {
        int tap = i / NF, f = i - tap * NF;
        fs[i] = filters[(f >> 1) * 450 + (f & 1) * 225 + tap];
    }
    const float* xp = x + (size_t)plane * PLANE;
    for (int i = tid; i < NCHUNK * XW; i += 256) {
        int rr = i / XW, cc = i - rr * XW;
        int gy = y0 + rr - 7, gx = cc - 7;
        xs[i] = (gy >= 0 && gy < HW && gx >= 0 && gx < HW) ? xp[gy * HW + gx] : 0.f;
    }
    __syncthreads();

    const int x0 = (tid & 63) * 2;
    const int ry = tid >> 6;
    const size_t mbase0 = ((size_t)b * CIN + (size_t)c * NSO) * PLANE
                        + (size_t)(y0 + ry) * HW + x0;
    for (int g = 0; g < 4; ++g) {
        u64 acc[2][6];
#pragma unroll
        for (int p = 0; p < 2; ++p)
#pragma unroll
            for (int s = 0; s < 6; ++s) acc[p][s] = 0ull;
        for (int dy = 0; dy < KK; ++dy) {
            const float* xr = xs + (ry + dy) * XW + x0;
            const float* wr = fs + dy * KK * NF + g * 12;
#pragma unroll
            for (int dx = 0; dx < KK; ++dx) {
                const float* w = wr + dx * NF;
                ulonglong2 wa = *(const ulonglong2*)(w);
                ulonglong2 wb = *(const ulonglong2*)(w + 4);
                ulonglong2 wc = *(const ulonglong2*)(w + 8);
                u64 wp[6] = {wa.x, wa.y, wb.x, wb.y, wc.x, wc.y};
                u64 xv[2] = {splat(xr[dx]), splat(xr[dx + 1])};
#pragma unroll
                for (int p = 0; p < 2; ++p)
#pragma unroll
                    for (int s = 0; s < 6; ++s) fma2(acc[p][s], xv[p], wp[s]);
            }
        }
#pragma unroll
        for (int s = 0; s < 6; ++s) {
            float re0, im0, re1, im1;
            upk2(acc[0][s], re0, im0);
            upk2(acc[1][s], re1, im1);
            float2 m = make_float2(sqrtf(re0*re0 + im0*im0), sqrtf(re1*re1 + im1*im1));
            *(float2*)(g_mag + mbase0 + (size_t)(g * 6 + s) * PLANE) = m;
        }
    }
#endif
}

// ---------------------------------------------------------------------------
// Kernel B: channel mix (FFMA2), bias dropped (cancels in instance norm)
// ---------------------------------------------------------------------------
static const int SMEM_MIX = CIN * 32 * 4;

__global__ __launch_bounds__(256, 2)
void mix_kernel(const float* __restrict__ w1) {
    extern __shared__ float w1s[];
    const int tid = threadIdx.x;
    for (int i = tid; i < CIN * 32; i += 256) {
        int j = i >> 5, o = i & 31;
        w1s[i] = w1[o * CIN + j];
    }
    __syncthreads();

    const int bb = blockIdx.y;
    const int q0 = blockIdx.x * 512 + tid * 2;
    const float* mp = g_mag + (size_t)bb * CIN * PLANE + q0;

    u64 acc[16][2];
#pragma unroll
    for (int op = 0; op < 16; ++op) { acc[op][0] = 0ull; acc[op][1] = 0ull; }

#pragma unroll 4
    for (int j = 0; j < CIN; ++j) {
        float2 m = *(const float2*)(mp + (size_t)j * PLANE);
        u64 mx = splat(m.x), my = splat(m.y);
        const ulonglong2* wrow = (const ulonglong2*)(w1s + j * 32);
#pragma unroll
        for (int q4 = 0; q4 < 8; ++q4) {
            ulonglong2 w2 = wrow[q4];
            fma2(acc[q4 * 2 + 0][0], mx, w2.x);
            fma2(acc[q4 * 2 + 0][1], my, w2.x);
            fma2(acc[q4 * 2 + 1][0], mx, w2.y);
            fma2(acc[q4 * 2 + 1][1], my, w2.y);
        }
    }
#pragma unroll
    for (int op = 0; op < 16; ++op) {
        float a0lo, a0hi, a1lo, a1hi;
        upk2(acc[op][0], a0lo, a0hi);
        upk2(acc[op][1], a1lo, a1hi);
        *(float2*)(g_z + (size_t)(bb * 32 + 2 * op)     * PLANE + q0) = make_float2(a0lo, a1lo);
        *(float2*)(g_z + (size_t)(bb * 32 + 2 * op + 1) * PLANE + q0) = make_float2(a0hi, a1hi);
    }
}

// ---------------------------------------------------------------------------
__global__ void stats_kernel() {
    const int plane = blockIdx.x;
    const float* zp = g_z + (size_t)plane * PLANE;
    const int tid = threadIdx.x;
    float s = 0.f, s2 = 0.f;
    for (int i = tid * 4; i < PLANE; i += 1024) {
        float4 v = *(const float4*)(zp + i);
        s  += v.x + v.y + v.z + v.w;
        s2 += v.x * v.x + v.y * v.y + v.z * v.z + v.w * v.w;
    }
    __shared__ float r1[256], r2[256];
    r1[tid] = s; r2[tid] = s2;
    __syncthreads();
    for (int st = 128; st > 0; st >>= 1) {
        if (tid < st) { r1[tid] += r1[tid + st]; r2[tid] += r2[tid + st]; }
        __syncthreads();
    }
    if (tid == 0) {
        float mean = r1[0] * (1.f / PLANE);
        float var  = r2[0] * (1.f / PLANE) - mean * mean;
        g_stats[plane * 2]     = mean;
        g_stats[plane * 2 + 1] = rsqrtf(var + 1e-5f);
    }
}

__global__ void norm_kernel(float* __restrict__ out) {
    __shared__ float s[32][33];
    const int plane = blockIdx.y;
    const int tile  = blockIdx.x;
    const int hb = (tile >> 2) * 32, wb = (tile & 3) * 32;
    const float mean = g_stats[plane * 2];
    const float rstd = g_stats[plane * 2 + 1];
    const float* zp = g_z + (size_t)plane * PLANE;
    float* op = out + (size_t)plane * PLANE;
    const int cc = threadIdx.x & 31;
    const int r0 = threadIdx.x >> 5;
#pragma unroll
    for (int k = 0; k < 4; ++k) {
        int rr = r0 + k * 8;
        s[rr][cc] = zp[(wb + rr) * HW + hb + cc];
    }
    __syncthreads();
#pragma unroll
    for (int k = 0; k < 4; ++k) {
        int rr = r0 + k * 8;
        op[(hb + rr) * HW + wb + cc] = (s[cc][rr] - mean) * rstd;
    }
}

// ---------------------------------------------------------------------------
extern "C" void kernel_launch(void* const* d_in, const int* in_sizes, int n_in,
                              void* d_out, int out_size) {
    const float* x       = (const float*)d_in[0];
    const float* filters = (const float*)d_in[1];
    const float* w1      = (const float*)d_in[2];
    float* out = (float*)d_out;

    cudaFuncSetAttribute(gabor_mma_kernel, cudaFuncAttributeMaxDynamicSharedMemorySize, SMEM_GABOR);
    cudaFuncSetAttribute(mix_kernel,       cudaFuncAttributeMaxDynamicSharedMemorySize, SMEM_MIX);

    gabor_mma_kernel<<<dim3(32, 128), 256, SMEM_GABOR>>>(x, filters);
    mix_kernel<<<dim3(32, 4), 256, SMEM_MIX>>>(w1);
    stats_kernel<<<128, 256>>>();
    norm_kernel<<<dim3(16, 128), 256>>>(out);
}

// round 8
// speedup vs baseline: 2.8365x; 2.8360x over previous
#include <cuda_runtime.h>
#include <cstdint>
#include <math.h>

#define KK     15
#define HW     128
#define PLANE  16384
#define CIN    768
#define NSO    24
#define NF     48          // filters (N dim)
#define RT     4           // output rows per CTA
#define ARING  6           // TMEM A-chunk ring slots
#define NCHUNK 18          // RT + 14 input rows per CTA

// ---- smem layout (bytes) for tcgen05 path ----
#define SM_TMEM   0
#define SM_MBAR   64                 // 15 mbarriers x 8B
#define SM_B      1024               // 4 B-slots x 6144B (48 rows x 128B, SW128)
#define SLOT_BF   6144
#define SM_X      (SM_B + 4*SLOT_BF) // 25600: 18 x-rows x 128 floats
// tcgen05 path needs ~34816; fallback needs 53568. Launch with max.
#define SMEM_GABOR 53568

// TMEM columns: D tiles at r*64 (r=0..3); A ring at 256 + slot*32 (slots 0..5)
#define TM_A0  256

// idesc: dfmt=F32(1)<<4 | afmt=TF32(2)<<7 | bfmt=TF32(2)<<10 | (N/8)<<17 | (M/16)<<24
#define IDESC_TF32 ((1u<<4) | (2u<<7) | (2u<<10) | ((NF/8)<<17) | ((128/16)<<24))

#if defined(__CUDA_ARCH__) && (defined(__CUDA_ARCH_FEAT_SM103_ALL) || defined(__CUDA_ARCH_SPECIFIC__))
#define HAS_TCGEN05 1
#else
#define HAS_TCGEN05 0
#endif

typedef unsigned long long u64;

// Scratch (.bss)
__device__ float g_mag[(size_t)4 * CIN * PLANE];   // [b][c*24+so][y*128+x]
__device__ float g_z[(size_t)128 * PLANE];
__device__ float g_stats[256];

// ---------------- portable helpers ----------------
__device__ __forceinline__ u64 splat(float v) {
    u64 r; asm("mov.b64 %0, {%1,%1};" : "=l"(r) : "f"(v)); return r;
}
__device__ __forceinline__ void fma2(u64& d, u64 a, u64 b) {
    asm("fma.rn.f32x2 %0, %1, %2, %0;" : "+l"(d) : "l"(a), "l"(b));
}
__device__ __forceinline__ void upk2(u64 v, float& lo, float& hi) {
    asm("mov.b64 {%0,%1}, %2;" : "=f"(lo), "=f"(hi) : "l"(v));
}

#if HAS_TCGEN05
// ---------------- sm_103a-only helpers ----------------
__device__ __forceinline__ uint32_t smem_u32(const void* p) {
    uint32_t a;
    asm("{ .reg .u64 t; cvta.to.shared.u64 t, %1; cvt.u32.u64 %0, t; }" : "=r"(a) : "l"(p));
    return a;
}
__device__ __forceinline__ uint32_t elect1() {
    uint32_t p;
    asm volatile("{ .reg .pred p; elect.sync _|p, 0xFFFFFFFF; selp.b32 %0,1,0,p; }" : "=r"(p));
    return p;
}
__device__ __forceinline__ float tf32r(float v) {
    uint32_t r; asm("cvt.rna.tf32.f32 %0, %1;" : "=r"(r) : "f"(v));
    return __uint_as_float(r);
}
#define SWZ(o) ((o) ^ ((((uint32_t)(o)) >> 3) & 0x70))

static __device__ __forceinline__ uint64_t mkdesc(uint32_t addr) {
    const uint64_t base = (uint64_t(2) << 61) | (uint64_t(1) << 46)
                        | (uint64_t(64) << 32) | (uint64_t(1) << 16);  // SW128
    return base | ((uint64_t)(addr >> 4) & 0x3FFF);
}
__device__ __forceinline__ void tmem_alloc(uint32_t smem_addr, uint32_t ncols) {
    asm volatile("tcgen05.alloc.cta_group::1.sync.aligned.shared::cta.b32 [%0], %1;"
                 :: "r"(smem_addr), "r"(ncols) : "memory");
}
__device__ __forceinline__ void tmem_relinq() {
    asm volatile("tcgen05.relinquish_alloc_permit.cta_group::1.sync.aligned;");
}
__device__ __forceinline__ void tmem_dealloc(uint32_t tmem, uint32_t ncols) {
    asm volatile("tcgen05.dealloc.cta_group::1.sync.aligned.b32 %0, %1;" :: "r"(tmem), "r"(ncols));
}
__device__ __forceinline__ void mbar_init(uint32_t a, uint32_t cnt) {
    asm volatile("mbarrier.init.shared.b64 [%0], %1;" :: "r"(a), "r"(cnt) : "memory");
}
__device__ __forceinline__ void mbar_inval(uint32_t a) {
    asm volatile("mbarrier.inval.shared.b64 [%0];" :: "r"(a) : "memory");
}
__device__ __forceinline__ void mbar_wait(uint32_t a, uint32_t par) {
    uint32_t done;
    asm volatile("{ .reg .pred p; mbarrier.try_wait.parity.acquire.cta.shared::cta.b64 p, [%1], %2;"
                 " selp.b32 %0,1,0,p; }" : "=r"(done) : "r"(a), "r"(par) : "memory");
    if (!done) {
        asm volatile("{ .reg .pred P1; WL_%=: mbarrier.try_wait.parity.acquire.cta.shared::cta.b64 P1, [%0], %1, 0x989680;"
                     " @P1 bra.uni WD_%=; bra.uni WL_%=; WD_%=: }" :: "r"(a), "r"(par) : "memory");
    }
}
__device__ __forceinline__ void mma_commit(uint32_t mbar) {
    asm volatile("tcgen05.commit.cta_group::1.mbarrier::arrive::one.shared::cluster.b64 [%0];"
                 :: "r"(mbar) : "memory");
}
// TS form: A in TMEM, B via SMEM descriptor
__device__ __forceinline__ void mma_tf32_ts(uint32_t d, uint32_t a, uint64_t bd, uint32_t en) {
    asm volatile("{ .reg .pred p; setp.ne.u32 p, %4, 0;"
                 " tcgen05.mma.cta_group::1.kind::tf32 [%0], [%1], %2, %3, {%5,%5,%5,%5}, p; }"
                 :: "r"(d), "r"(a), "l"(bd), "r"(IDESC_TF32), "r"(en), "r"(0u) : "memory");
}
__device__ __forceinline__ void fence_async_shared() {
    asm volatile("fence.proxy.async.shared::cta;" ::: "memory");
}
__device__ __forceinline__ void tc_fence_before() {
    asm volatile("tcgen05.fence::before_thread_sync;" ::: "memory");
}
__device__ __forceinline__ void tc_fence_after() {
    asm volatile("tcgen05.fence::after_thread_sync;" ::: "memory");
}
__device__ __forceinline__ void tc_wait_st() {
    asm volatile("tcgen05.wait::st.sync.aligned;" ::: "memory");
}
__device__ __forceinline__ void tc_wait_ld() {
    asm volatile("tcgen05.wait::ld.sync.aligned;" ::: "memory");
}
__device__ __forceinline__ void sttm_x32(uint32_t a, const uint32_t* r) {
    asm volatile("tcgen05.st.sync.aligned.32x32b.x32.b32 [%0], "
        "{%1,%2,%3,%4,%5,%6,%7,%8,%9,%10,%11,%12,%13,%14,%15,%16,"
        "%17,%18,%19,%20,%21,%22,%23,%24,%25,%26,%27,%28,%29,%30,%31,%32};"
        :: "r"(a),
           "r"(r[0]),"r"(r[1]),"r"(r[2]),"r"(r[3]),"r"(r[4]),"r"(r[5]),"r"(r[6]),"r"(r[7]),
           "r"(r[8]),"r"(r[9]),"r"(r[10]),"r"(r[11]),"r"(r[12]),"r"(r[13]),"r"(r[14]),"r"(r[15]),
           "r"(r[16]),"r"(r[17]),"r"(r[18]),"r"(r[19]),"r"(r[20]),"r"(r[21]),"r"(r[22]),"r"(r[23]),
           "r"(r[24]),"r"(r[25]),"r"(r[26]),"r"(r[27]),"r"(r[28]),"r"(r[29]),"r"(r[30]),"r"(r[31])
        : "memory");
}
__device__ __forceinline__ void ldtm_x32(uint32_t* r, uint32_t a) {
    asm volatile("tcgen05.ld.sync.aligned.32x32b.x32.b32 "
        "{%0,%1,%2,%3,%4,%5,%6,%7,%8,%9,%10,%11,%12,%13,%14,%15,"
        "%16,%17,%18,%19,%20,%21,%22,%23,%24,%25,%26,%27,%28,%29,%30,%31}, [%32];"
        : "=r"(r[0]),"=r"(r[1]),"=r"(r[2]),"=r"(r[3]),"=r"(r[4]),"=r"(r[5]),"=r"(r[6]),"=r"(r[7]),
          "=r"(r[8]),"=r"(r[9]),"=r"(r[10]),"=r"(r[11]),"=r"(r[12]),"=r"(r[13]),"=r"(r[14]),"=r"(r[15]),
          "=r"(r[16]),"=r"(r[17]),"=r"(r[18]),"=r"(r[19]),"=r"(r[20]),"=r"(r[21]),"=r"(r[22]),"=r"(r[23]),
          "=r"(r[24]),"=r"(r[25]),"=r"(r[26]),"=r"(r[27]),"=r"(r[28]),"=r"(r[29]),"=r"(r[30]),"=r"(r[31])
        : "r"(a));
}
__device__ __forceinline__ void ldtm_x16(uint32_t* r, uint32_t a) {
    asm volatile("tcgen05.ld.sync.aligned.32x32b.x16.b32 "
        "{%0,%1,%2,%3,%4,%5,%6,%7,%8,%9,%10,%11,%12,%13,%14,%15}, [%16];"
        : "=r"(r[0]),"=r"(r[1]),"=r"(r[2]),"=r"(r[3]),"=r"(r[4]),"=r"(r[5]),"=r"(r[6]),"=r"(r[7]),
          "=r"(r[8]),"=r"(r[9]),"=r"(r[10]),"=r"(r[11]),"=r"(r[12]),"=r"(r[13]),"=r"(r[14]),"=r"(r[15])
        : "r"(a));
}

// im2col chunk builder (A split: cols 0-15 hi(tf32), 16-31 lo(tf32 of residual))
__device__ __forceinline__ void build_chunk(char* smem, uint32_t tmem_a, int ci, int wid, int lid) {
    const float* xr = (const float*)(smem + SM_X) + ci * HW;
    const int xpos = (wid << 5) + lid;
    uint32_t regs[32];
#pragma unroll
    for (int dx = 0; dx < 16; ++dx) {
        int sx = xpos + dx - 7;
        float v = (dx < 15 && sx >= 0 && sx < HW) ? xr[sx] : 0.f;
        float hi = tf32r(v);
        regs[dx]      = __float_as_uint(hi);
        regs[16 + dx] = __float_as_uint(tf32r(v - hi));
    }
    sttm_x32(tmem_a + ((uint32_t)wid << 21), regs);
}
// Filters for one dy into SMEM (SW128): hi only, cols 0-15. Threads 128-255.
__device__ __forceinline__ void build_filt(char* smem, int boff, const float* __restrict__ filters,
                                           int dy, int t) {
    for (int i = t; i < NF * 16; i += 128) {
        int f = i >> 4, dx = i & 15;
        float v = (dx < 15) ? filters[(f >> 1) * 450 + (f & 1) * 225 + dy * 15 + dx] : 0.f;
        *(float*)(smem + boff + SWZ(f * 128 + dx * 4)) = tf32r(v);
    }
}
#endif  // HAS_TCGEN05

// ---------------------------------------------------------------------------
// Kernel A: Gabor conv + magnitude.
// sm_103a: tcgen05 tf32 TS-mode implicit GEMM.
// 2-term split: D = (Ahi + Alo) x Bhi  (A exact fp32, B rounded once to tf32).
// grid (32 row-groups, 128 planes), 256 threads, occ 1
// ---------------------------------------------------------------------------
__global__ __launch_bounds__(256, 1)
void gabor_mma_kernel(const float* __restrict__ x, const float* __restrict__ filters) {
#if HAS_TCGEN05
    extern __shared__ char smem[];
    const uint32_t sb = smem_u32(smem);
    const int tid = threadIdx.x, wid = tid >> 5, lid = tid & 31;
    const int plane = blockIdx.y;
    const int y0 = blockIdx.x * RT;
    const int b = plane >> 5, c = plane & 31;

    if (wid == 0) tmem_alloc(sb + SM_TMEM, 512);
    if (tid == 0)
        for (int i = 0; i < KK; ++i) mbar_init(sb + SM_MBAR + i * 8, 1);

    // stage NCHUNK x-rows (zero-padded in y)
    const float* xp = x + (size_t)plane * PLANE;
    float* xs = (float*)(smem + SM_X);
    for (int i = tid; i < NCHUNK * HW; i += 256) {
        int rr = i >> 7, cc = i & 127;
        int gy = y0 + rr - 7;
        xs[i] = (gy >= 0 && gy < HW) ? xp[gy * HW + cc] : 0.f;
    }
    __syncthreads();
    uint32_t tmem;
    asm volatile("ld.shared.b32 %0, [%1];" : "=r"(tmem) : "r"(sb + SM_TMEM));
    if (wid == 0) tmem_relinq();

    // prebuild A chunks 0..2 into TMEM ring slots 0..2
    if (wid < 4) {
        for (int ci = 0; ci < RT - 1; ++ci)
            build_chunk(smem, tmem + TM_A0 + ci * 32, ci, wid, lid);
        tc_wait_st();
    }

    for (int dy = 0; dy < KK; ++dy) {
        if (dy >= 3) mbar_wait(sb + SM_MBAR + (dy - 3) * 8, 0);   // depth-3 pipeline
        if (wid < 4) {
            build_chunk(smem, tmem + TM_A0 + ((dy + 3) % ARING) * 32, dy + 3, wid, lid);
            tc_wait_st();
        } else {
            build_filt(smem, SM_B + (dy & 3) * SLOT_BF, filters, dy, tid - 128);
        }
        tc_fence_before();
        fence_async_shared();
        __syncthreads();
        if (wid == 0) {
            tc_fence_after();
            if (elect1()) {
                uint64_t bd = mkdesc(sb + SM_B + (dy & 3) * SLOT_BF);
#pragma unroll
                for (int r = 0; r < RT; ++r) {
                    uint32_t a = tmem + TM_A0 + ((dy + r) % ARING) * 32;
                    uint32_t d = tmem + r * 64;
                    mma_tf32_ts(d, a + 0,  bd + 0, dy > 0);  // hi x Bhi, k0
                    mma_tf32_ts(d, a + 8,  bd + 2, 1);       // hi x Bhi, k1
                    mma_tf32_ts(d, a + 16, bd + 0, 1);       // lo x Bhi, k0
                    mma_tf32_ts(d, a + 24, bd + 2, 1);       // lo x Bhi, k1
                }
                mma_commit(sb + SM_MBAR + dy * 8);
            }
        }
    }
    mbar_wait(sb + SM_MBAR + (KK - 1) * 8, 0);
    tc_fence_after();

    // epilogue: warps 0-3 -> tiles 0,1 ; warps 4-7 -> tiles 2,3 ; sub = wid&3
    const int sub = wid & 3;
    const int xc = sub * 32 + lid;
    const size_t mbase = ((size_t)b * CIN + (size_t)c * NSO) * PLANE + xc;
#pragma unroll
    for (int rr = 0; rr < 2; ++rr) {
        const int r = (wid >> 2) * 2 + rr;
        uint32_t rg[48];
        ldtm_x32(rg, tmem + r * 64);
        ldtm_x16(rg + 32, tmem + r * 64 + 32);
        tc_wait_ld();
        const int y = y0 + r;
#pragma unroll
        for (int s = 0; s < NSO; ++s) {
            float re = __uint_as_float(rg[2 * s]);
            float im = __uint_as_float(rg[2 * s + 1]);
            g_mag[mbase + (size_t)s * PLANE + (size_t)y * HW] = sqrtf(re * re + im * im);
        }
    }
    __syncthreads();
    if (tid == 0)
        for (int i = 0; i < KK; ++i) mbar_inval(sb + SM_MBAR + i * 8);
    __syncthreads();
    if (wid == 0) tmem_dealloc(tmem, 512);

#else  // ---------------- scalar FFMA2 fallback (non-arch-specific pass) -----
    extern __shared__ float smf[];
    float* fs = smf;                        // [225][48]
    float* xs = smf + 225 * NF;             // [18][144]
    const int XW = 144;
    const int tid = threadIdx.x;
    const int plane = blockIdx.y;
    const int y0 = blockIdx.x * RT;
    const int b = plane >> 5, c = plane & 31;

    for (int i = tid; i < 225 * NF; i += 256) {
        int tap = i / NF, f = i - tap * NF;
        fs[i] = filters[(f >> 1) * 450 + (f & 1) * 225 + tap];
    }
    const float* xp = x + (size_t)plane * PLANE;
    for (int i = tid; i < NCHUNK * XW; i += 256) {
        int rr = i / XW, cc = i - rr * XW;
        int gy = y0 + rr - 7, gx = cc - 7;
        xs[i] = (gy >= 0 && gy < HW && gx >= 0 && gx < HW) ? xp[gy * HW + gx] : 0.f;
    }
    __syncthreads();

    const int x0 = (tid & 63) * 2;
    const int ry = tid >> 6;
    const size_t mbase0 = ((size_t)b * CIN + (size_t)c * NSO) * PLANE
                        + (size_t)(y0 + ry) * HW + x0;
    for (int g = 0; g < 4; ++g) {
        u64 acc[2][6];
#pragma unroll
        for (int p = 0; p < 2; ++p)
#pragma unroll
            for (int s = 0; s < 6; ++s) acc[p][s] = 0ull;
        for (int dy = 0; dy < KK; ++dy) {
            const float* xr = xs + (ry + dy) * XW + x0;
            const float* wr = fs + dy * KK * NF + g * 12;
#pragma unroll
            for (int dx = 0; dx < KK; ++dx) {
                const float* w = wr + dx * NF;
                ulonglong2 wa = *(const ulonglong2*)(w);
                ulonglong2 wb = *(const ulonglong2*)(w + 4);
                ulonglong2 wc = *(const ulonglong2*)(w + 8);
                u64 wp[6] = {wa.x, wa.y, wb.x, wb.y, wc.x, wc.y};
                u64 xv[2] = {splat(xr[dx]), splat(xr[dx + 1])};
#pragma unroll
                for (int p = 0; p < 2; ++p)
#pragma unroll
                    for (int s = 0; s < 6; ++s) fma2(acc[p][s], xv[p], wp[s]);
            }
        }
#pragma unroll
        for (int s = 0; s < 6; ++s) {
            float re0, im0, re1, im1;
            upk2(acc[0][s], re0, im0);
            upk2(acc[1][s], re1, im1);
            float2 m = make_float2(sqrtf(re0*re0 + im0*im0), sqrtf(re1*re1 + im1*im1));
            *(float2*)(g_mag + mbase0 + (size_t)(g * 6 + s) * PLANE) = m;
        }
    }
#endif
}

// ---------------------------------------------------------------------------
// Kernel B: channel mix (FFMA2), bias dropped (cancels in instance norm)
// ---------------------------------------------------------------------------
static const int SMEM_MIX = CIN * 32 * 4;

__global__ __launch_bounds__(256, 2)
void mix_kernel(const float* __restrict__ w1) {
    extern __shared__ float w1s[];
    const int tid = threadIdx.x;
    for (int i = tid; i < CIN * 32; i += 256) {
        int j = i >> 5, o = i & 31;
        w1s[i] = w1[o * CIN + j];
    }
    __syncthreads();

    const int bb = blockIdx.y;
    const int q0 = blockIdx.x * 512 + tid * 2;
    const float* mp = g_mag + (size_t)bb * CIN * PLANE + q0;

    u64 acc[16][2];
#pragma unroll
    for (int op = 0; op < 16; ++op) { acc[op][0] = 0ull; acc[op][1] = 0ull; }

#pragma unroll 4
    for (int j = 0; j < CIN; ++j) {
        float2 m = *(const float2*)(mp + (size_t)j * PLANE);
        u64 mx = splat(m.x), my = splat(m.y);
        const ulonglong2* wrow = (const ulonglong2*)(w1s + j * 32);
#pragma unroll
        for (int q4 = 0; q4 < 8; ++q4) {
            ulonglong2 w2 = wrow[q4];
            fma2(acc[q4 * 2 + 0][0], mx, w2.x);
            fma2(acc[q4 * 2 + 0][1], my, w2.x);
            fma2(acc[q4 * 2 + 1][0], mx, w2.y);
            fma2(acc[q4 * 2 + 1][1], my, w2.y);
        }
    }
#pragma unroll
    for (int op = 0; op < 16; ++op) {
        float a0lo, a0hi, a1lo, a1hi;
        upk2(acc[op][0], a0lo, a0hi);
        upk2(acc[op][1], a1lo, a1hi);
        *(float2*)(g_z + (size_t)(bb * 32 + 2 * op)     * PLANE + q0) = make_float2(a0lo, a1lo);
        *(float2*)(g_z + (size_t)(bb * 32 + 2 * op + 1) * PLANE + q0) = make_float2(a0hi, a1hi);
    }
}

// ---------------------------------------------------------------------------
__global__ void stats_kernel() {
    const int plane = blockIdx.x;
    const float* zp = g_z + (size_t)plane * PLANE;
    const int tid = threadIdx.x;
    float s = 0.f, s2 = 0.f;
    for (int i = tid * 4; i < PLANE; i += 1024) {
        float4 v = *(const float4*)(zp + i);
        s  += v.x + v.y + v.z + v.w;
        s2 += v.x * v.x + v.y * v.y + v.z * v.z + v.w * v.w;
    }
    __shared__ float r1[256], r2[256];
    r1[tid] = s; r2[tid] = s2;
    __syncthreads();
    for (int st = 128; st > 0; st >>= 1) {
        if (tid < st) { r1[tid] += r1[tid + st]; r2[tid] += r2[tid + st]; }
        __syncthreads();
    }
    if (tid == 0) {
        float mean = r1[0] * (1.f / PLANE);
        float var  = r2[0] * (1.f / PLANE) - mean * mean;
        g_stats[plane * 2]     = mean;
        g_stats[plane * 2 + 1] = rsqrtf(var + 1e-5f);
    }
}

__global__ void norm_kernel(float* __restrict__ out) {
    __shared__ float s[32][33];
    const int plane = blockIdx.y;
    const int tile  = blockIdx.x;
    const int hb = (tile >> 2) * 32, wb = (tile & 3) * 32;
    const float mean = g_stats[plane * 2];
    const float rstd = g_stats[plane * 2 + 1];
    const float* zp = g_z + (size_t)plane * PLANE;
    float* op = out + (size_t)plane * PLANE;
    const int cc = threadIdx.x & 31;
    const int r0 = threadIdx.x >> 5;
#pragma unroll
    for (int k = 0; k < 4; ++k) {
        int rr = r0 + k * 8;
        s[rr][cc] = zp[(wb + rr) * HW + hb + cc];
    }
    __syncthreads();
#pragma unroll
    for (int k = 0; k < 4; ++k) {
        int rr = r0 + k * 8;
        op[(hb + rr) * HW + wb + cc] = (s[cc][rr] - mean) * rstd;
    }
}

// ---------------------------------------------------------------------------
extern "C" void kernel_launch(void* const* d_in, const int* in_sizes, int n_in,
                              void* d_out, int out_size) {
    const float* x       = (const float*)d_in[0];
    const float* filters = (const float*)d_in[1];
    const float* w1      = (const float*)d_in[2];
    float* out = (float*)d_out;

    cudaFuncSetAttribute(gabor_mma_kernel, cudaFuncAttributeMaxDynamicSharedMemorySize, SMEM_GABOR);
    cudaFuncSetAttribute(mix_kernel,       cudaFuncAttributeMaxDynamicSharedMemorySize, SMEM_MIX);

    gabor_mma_kernel<<<dim3(32, 128), 256, SMEM_GABOR>>>(x, filters);
    mix_kernel<<<dim3(32, 4), 256, SMEM_MIX>>>(w1);
    stats_kernel<<<128, 256>>>();
    norm_kernel<<<dim3(16, 128), 256>>>(out);
}

// round 9
// speedup vs baseline: 3.3405x; 1.1777x over previous
#include <cuda_runtime.h>
#include <cstdint>
#include <math.h>

#define KK     15
#define HW     128
#define PLANE  16384
#define CIN    768
#define NSO    24
#define NF     48          // filters (N dim)
#define RT     4           // output rows per CTA
#define ARING  10          // TMEM A-chunk ring slots (32 cols each)
#define NCHUNK 18          // RT + 14 input rows per CTA
#define NROUND 8           // ceil(KK/2) sync rounds, 2 dy each

// ---- smem layout (bytes) for tcgen05 path ----
#define SM_TMEM   0
#define SM_MBAR   64                 // 8 mbarriers x 8B
#define SM_B      1024               // 4 B-slots x 6144B (48 rows x 128B, SW128)
#define SLOT_BF   6144
#define SM_X      (SM_B + 4*SLOT_BF) // 25600: 18 x-rows x 128 floats
// tcgen05 path needs ~34816; fallback needs 53568. Launch with max.
#define SMEM_GABOR 53568

// TMEM columns: D tiles at r*48 (r=0..3, 192 cols); A ring at 192 + slot*32
#define TM_A0  192
#define TM_DSTRIDE 48

// idesc: dfmt=F32(1)<<4 | afmt=TF32(2)<<7 | bfmt=TF32(2)<<10 | (N/8)<<17 | (M/16)<<24
#define IDESC_TF32 ((1u<<4) | (2u<<7) | (2u<<10) | ((NF/8)<<17) | ((128/16)<<24))

#if defined(__CUDA_ARCH__) && (defined(__CUDA_ARCH_FEAT_SM103_ALL) || defined(__CUDA_ARCH_SPECIFIC__))
#define HAS_TCGEN05 1
#else
#define HAS_TCGEN05 0
#endif

typedef unsigned long long u64;

// Scratch (.bss)
__device__ float g_mag[(size_t)4 * CIN * PLANE];   // [b][c*24+so][y*128+x]
__device__ float g_z[(size_t)128 * PLANE];
__device__ float g_stats[256];

// ---------------- portable helpers ----------------
__device__ __forceinline__ u64 splat(float v) {
    u64 r; asm("mov.b64 %0, {%1,%1};" : "=l"(r) : "f"(v)); return r;
}
__device__ __forceinline__ void fma2(u64& d, u64 a, u64 b) {
    asm("fma.rn.f32x2 %0, %1, %2, %0;" : "+l"(d) : "l"(a), "l"(b));
}
__device__ __forceinline__ void upk2(u64 v, float& lo, float& hi) {
    asm("mov.b64 {%0,%1}, %2;" : "=f"(lo), "=f"(hi) : "l"(v));
}

#if HAS_TCGEN05
// ---------------- sm_103a-only helpers ----------------
__device__ __forceinline__ uint32_t smem_u32(const void* p) {
    uint32_t a;
    asm("{ .reg .u64 t; cvta.to.shared.u64 t, %1; cvt.u32.u64 %0, t; }" : "=r"(a) : "l"(p));
    return a;
}
__device__ __forceinline__ uint32_t elect1() {
    uint32_t p;
    asm volatile("{ .reg .pred p; elect.sync _|p, 0xFFFFFFFF; selp.b32 %0,1,0,p; }" : "=r"(p));
    return p;
}
__device__ __forceinline__ float tf32r(float v) {
    uint32_t r; asm("cvt.rna.tf32.f32 %0, %1;" : "=r"(r) : "f"(v));
    return __uint_as_float(r);
}
#define SWZ(o) ((o) ^ ((((uint32_t)(o)) >> 3) & 0x70))

static __device__ __forceinline__ uint64_t mkdesc(uint32_t addr) {
    const uint64_t base = (uint64_t(2) << 61) | (uint64_t(1) << 46)
                        | (uint64_t(64) << 32) | (uint64_t(1) << 16);  // SW128
    return base | ((uint64_t)(addr >> 4) & 0x3FFF);
}
__device__ __forceinline__ void tmem_alloc(uint32_t smem_addr, uint32_t ncols) {
    asm volatile("tcgen05.alloc.cta_group::1.sync.aligned.shared::cta.b32 [%0], %1;"
                 :: "r"(smem_addr), "r"(ncols) : "memory");
}
__device__ __forceinline__ void tmem_relinq() {
    asm volatile("tcgen05.relinquish_alloc_permit.cta_group::1.sync.aligned;");
}
__device__ __forceinline__ void tmem_dealloc(uint32_t tmem, uint32_t ncols) {
    asm volatile("tcgen05.dealloc.cta_group::1.sync.aligned.b32 %0, %1;" :: "r"(tmem), "r"(ncols));
}
__device__ __forceinline__ void mbar_init(uint32_t a, uint32_t cnt) {
    asm volatile("mbarrier.init.shared.b64 [%0], %1;" :: "r"(a), "r"(cnt) : "memory");
}
__device__ __forceinline__ void mbar_inval(uint32_t a) {
    asm volatile("mbarrier.inval.shared.b64 [%0];" :: "r"(a) : "memory");
}
__device__ __forceinline__ void mbar_wait(uint32_t a, uint32_t par) {
    uint32_t done;
    asm volatile("{ .reg .pred p; mbarrier.try_wait.parity.acquire.cta.shared::cta.b64 p, [%1], %2;"
                 " selp.b32 %0,1,0,p; }" : "=r"(done) : "r"(a), "r"(par) : "memory");
    if (!done) {
        asm volatile("{ .reg .pred P1; WL_%=: mbarrier.try_wait.parity.acquire.cta.shared::cta.b64 P1, [%0], %1, 0x989680;"
                     " @P1 bra.uni WD_%=; bra.uni WL_%=; WD_%=: }" :: "r"(a), "r"(par) : "memory");
    }
}
__device__ __forceinline__ void mma_commit(uint32_t mbar) {
    asm volatile("tcgen05.commit.cta_group::1.mbarrier::arrive::one.shared::cluster.b64 [%0];"
                 :: "r"(mbar) : "memory");
}
// TS form: A in TMEM, B via SMEM descriptor
__device__ __forceinline__ void mma_tf32_ts(uint32_t d, uint32_t a, uint64_t bd, uint32_t en) {
    asm volatile("{ .reg .pred p; setp.ne.u32 p, %4, 0;"
                 " tcgen05.mma.cta_group::1.kind::tf32 [%0], [%1], %2, %3, {%5,%5,%5,%5}, p; }"
                 :: "r"(d), "r"(a), "l"(bd), "r"(IDESC_TF32), "r"(en), "r"(0u) : "memory");
}
__device__ __forceinline__ void fence_async_shared() {
    asm volatile("fence.proxy.async.shared::cta;" ::: "memory");
}
__device__ __forceinline__ void tc_fence_before() {
    asm volatile("tcgen05.fence::before_thread_sync;" ::: "memory");
}
__device__ __forceinline__ void tc_fence_after() {
    asm volatile("tcgen05.fence::after_thread_sync;" ::: "memory");
}
__device__ __forceinline__ void tc_wait_st() {
    asm volatile("tcgen05.wait::st.sync.aligned;" ::: "memory");
}
__device__ __forceinline__ void tc_wait_ld() {
    asm volatile("tcgen05.wait::ld.sync.aligned;" ::: "memory");
}
__device__ __forceinline__ void sttm_x32(uint32_t a, const uint32_t* r) {
    asm volatile("tcgen05.st.sync.aligned.32x32b.x32.b32 [%0], "
        "{%1,%2,%3,%4,%5,%6,%7,%8,%9,%10,%11,%12,%13,%14,%15,%16,"
        "%17,%18,%19,%20,%21,%22,%23,%24,%25,%26,%27,%28,%29,%30,%31,%32};"
        :: "r"(a),
           "r"(r[0]),"r"(r[1]),"r"(r[2]),"r"(r[3]),"r"(r[4]),"r"(r[5]),"r"(r[6]),"r"(r[7]),
           "r"(r[8]),"r"(r[9]),"r"(r[10]),"r"(r[11]),"r"(r[12]),"r"(r[13]),"r"(r[14]),"r"(r[15]),
           "r"(r[16]),"r"(r[17]),"r"(r[18]),"r"(r[19]),"r"(r[20]),"r"(r[21]),"r"(r[22]),"r"(r[23]),
           "r"(r[24]),"r"(r[25]),"r"(r[26]),"r"(r[27]),"r"(r[28]),"r"(r[29]),"r"(r[30]),"r"(r[31])
        : "memory");
}
__device__ __forceinline__ void ldtm_x16(uint32_t* r, uint32_t a) {
    asm volatile("tcgen05.ld.sync.aligned.32x32b.x16.b32 "
        "{%0,%1,%2,%3,%4,%5,%6,%7,%8,%9,%10,%11,%12,%13,%14,%15}, [%16];"
        : "=r"(r[0]),"=r"(r[1]),"=r"(r[2]),"=r"(r[3]),"=r"(r[4]),"=r"(r[5]),"=r"(r[6]),"=r"(r[7]),
          "=r"(r[8]),"=r"(r[9]),"=r"(r[10]),"=r"(r[11]),"=r"(r[12]),"=r"(r[13]),"=r"(r[14]),"=r"(r[15])
        : "r"(a));
}

// im2col chunk builder (A split: cols 0-15 hi(tf32), 16-31 lo(tf32 of residual))
__device__ __forceinline__ void build_chunk(char* smem, uint32_t tmem_a, int ci, int wid, int lid) {
    const float* xr = (const float*)(smem + SM_X) + ci * HW;
    const int xpos = (wid << 5) + lid;
    uint32_t regs[32];
#pragma unroll
    for (int dx = 0; dx < 16; ++dx) {
        int sx = xpos + dx - 7;
        float v = (dx < 15 && sx >= 0 && sx < HW) ? xr[sx] : 0.f;
        float hi = tf32r(v);
        regs[dx]      = __float_as_uint(hi);
        regs[16 + dx] = __float_as_uint(tf32r(v - hi));
    }
    sttm_x32(tmem_a + ((uint32_t)wid << 21), regs);
}
// Filters for one dy into SMEM (SW128): cols 0-15 hi, 16-31 lo. Threads 128-255.
__device__ __forceinline__ void build_filt(char* smem, int boff, const float* __restrict__ filters,
                                           int dy, int t) {
    for (int i = t; i < NF * 32; i += 128) {
        int f = i >> 5, col = i & 31, dx = col & 15;
        float v = (dx < 15) ? filters[(f >> 1) * 450 + (f & 1) * 225 + dy * 15 + dx] : 0.f;
        float hi = tf32r(v);
        float val = (col >= 16) ? tf32r(v - hi) : hi;
        *(float*)(smem + boff + SWZ(f * 128 + col * 4)) = val;
    }
}
#endif  // HAS_TCGEN05

// ---------------------------------------------------------------------------
// Kernel A: Gabor conv + magnitude.
// sm_103a: tcgen05 tf32 TS-mode implicit GEMM, 3xTF32 split,
//          2 dy per sync round (8 rounds), ring-10 A, D stride 48.
// grid (32 row-groups, 128 planes), 256 threads, occ 1
// ---------------------------------------------------------------------------
__global__ __launch_bounds__(256, 1)
void gabor_mma_kernel(const float* __restrict__ x, const float* __restrict__ filters) {
#if HAS_TCGEN05
    extern __shared__ char smem[];
    const uint32_t sb = smem_u32(smem);
    const int tid = threadIdx.x, wid = tid >> 5, lid = tid & 31;
    const int plane = blockIdx.y;
    const int y0 = blockIdx.x * RT;
    const int b = plane >> 5, c = plane & 31;

    if (wid == 0) tmem_alloc(sb + SM_TMEM, 512);
    if (tid == 0)
        for (int i = 0; i < NROUND; ++i) mbar_init(sb + SM_MBAR + i * 8, 1);

    // stage NCHUNK x-rows (zero-padded in y)
    const float* xp = x + (size_t)plane * PLANE;
    float* xs = (float*)(smem + SM_X);
    for (int i = tid; i < NCHUNK * HW; i += 256) {
        int rr = i >> 7, cc = i & 127;
        int gy = y0 + rr - 7;
        xs[i] = (gy >= 0 && gy < HW) ? xp[gy * HW + cc] : 0.f;
    }
    __syncthreads();
    uint32_t tmem;
    asm volatile("ld.shared.b32 %0, [%1];" : "=r"(tmem) : "r"(sb + SM_TMEM));
    if (wid == 0) tmem_relinq();

    // prebuild A chunks 0..4 into ring slots 0..4
    if (wid < 4) {
        for (int ci = 0; ci < 5; ++ci)
            build_chunk(smem, tmem + TM_A0 + (ci % ARING) * 32, ci, wid, lid);
        tc_wait_st();
    }

    for (int rd = 0; rd < NROUND; ++rd) {
        const int dy0 = rd * 2;
        if (rd >= 2) mbar_wait(sb + SM_MBAR + (rd - 2) * 8, 0);   // depth-2 rounds
        if (wid < 4) {
#pragma unroll
            for (int j = 0; j < 2; ++j) {
                int ci = dy0 + 5 + j;
                if (ci < NCHUNK)
                    build_chunk(smem, tmem + TM_A0 + (ci % ARING) * 32, ci, wid, lid);
            }
            tc_wait_st();
        } else {
#pragma unroll
            for (int j = 0; j < 2; ++j) {
                int dy = dy0 + j;
                if (dy < KK)
                    build_filt(smem, SM_B + ((rd & 1) * 2 + j) * SLOT_BF, filters, dy, tid - 128);
            }
        }
        tc_fence_before();
        fence_async_shared();
        __syncthreads();
        if (wid == 0) {
            tc_fence_after();
            if (elect1()) {
#pragma unroll
                for (int j = 0; j < 2; ++j) {
                    int dy = dy0 + j;
                    if (dy >= KK) break;
                    uint64_t bd = mkdesc(sb + SM_B + ((rd & 1) * 2 + j) * SLOT_BF);
#pragma unroll
                    for (int r = 0; r < RT; ++r) {
                        uint32_t a = tmem + TM_A0 + ((dy + r) % ARING) * 32;
                        uint32_t d = tmem + r * TM_DSTRIDE;
                        mma_tf32_ts(d, a + 0,  bd + 0, dy > 0);  // hi x Bhi, k0
                        mma_tf32_ts(d, a + 8,  bd + 2, 1);       // hi x Bhi, k1
                        mma_tf32_ts(d, a + 16, bd + 0, 1);       // lo x Bhi, k0
                        mma_tf32_ts(d, a + 24, bd + 2, 1);       // lo x Bhi, k1
                        mma_tf32_ts(d, a + 0,  bd + 4, 1);       // hi x Blo, k0
                        mma_tf32_ts(d, a + 8,  bd + 6, 1);       // hi x Blo, k1
                    }
                }
                mma_commit(sb + SM_MBAR + rd * 8);
            }
        }
    }
    mbar_wait(sb + SM_MBAR + (NROUND - 1) * 8, 0);
    tc_fence_after();

    // epilogue: warps 0-3 -> tiles 0,1 ; warps 4-7 -> tiles 2,3 ; sub = wid&3
    const int sub = wid & 3;
    const int xc = sub * 32 + lid;
    const size_t mbase = ((size_t)b * CIN + (size_t)c * NSO) * PLANE + xc;
#pragma unroll
    for (int rr = 0; rr < 2; ++rr) {
        const int r = (wid >> 2) * 2 + rr;
        uint32_t rg[48];
        ldtm_x16(rg,      tmem + r * TM_DSTRIDE);
        ldtm_x16(rg + 16, tmem + r * TM_DSTRIDE + 16);
        ldtm_x16(rg + 32, tmem + r * TM_DSTRIDE + 32);
        tc_wait_ld();
        const int y = y0 + r;
#pragma unroll
        for (int s = 0; s < NSO; ++s) {
            float re = __uint_as_float(rg[2 * s]);
            float im = __uint_as_float(rg[2 * s + 1]);
            g_mag[mbase + (size_t)s * PLANE + (size_t)y * HW] = sqrtf(re * re + im * im);
        }
    }
    __syncthreads();
    if (tid == 0)
        for (int i = 0; i < NROUND; ++i) mbar_inval(sb + SM_MBAR + i * 8);
    __syncthreads();
    if (wid == 0) tmem_dealloc(tmem, 512);

#else  // ---------------- scalar FFMA2 fallback (non-arch-specific pass) -----
    extern __shared__ float smf[];
    float* fs = smf;                        // [225][48]
    float* xs = smf + 225 * NF;             // [18][144]
    const int XW = 144;
    const int tid = threadIdx.x;
    const int plane = blockIdx.y;
    const int y0 = blockIdx.x * RT;
    const int b = plane >> 5, c = plane & 31;

    for (int i = tid; i < 225 * NF; i += 256) {
        int tap = i / NF, f = i - tap * NF;
        fs[i] = filters[(f >> 1) * 450 + (f & 1) * 225 + tap];
    }
    const float* xp = x + (size_t)plane * PLANE;
    for (int i = tid; i < NCHUNK * XW; i += 256) {
        int rr = i / XW, cc = i - rr * XW;
        int gy = y0 + rr - 7, gx = cc - 7;
        xs[i] = (gy >= 0 && gy < HW && gx >= 0 && gx < HW) ? xp[gy * HW + gx] : 0.f;
    }
    __syncthreads();

    const int x0 = (tid & 63) * 2;
    const int ry = tid >> 6;
    const size_t mbase0 = ((size_t)b * CIN + (size_t)c * NSO) * PLANE
                        + (size_t)(y0 + ry) * HW + x0;
    for (int g = 0; g < 4; ++g) {
        u64 acc[2][6];
#pragma unroll
        for (int p = 0; p < 2; ++p)
#pragma unroll
            for (int s = 0; s < 6; ++s) acc[p][s] = 0ull;
        for (int dy = 0; dy < KK; ++dy) {
            const float* xr = xs + (ry + dy) * XW + x0;
            const float* wr = fs + dy * KK * NF + g * 12;
#pragma unroll
            for (int dx = 0; dx < KK; ++dx) {
                const float* w = wr + dx * NF;
                ulonglong2 wa = *(const ulonglong2*)(w);
                ulonglong2 wb = *(const ulonglong2*)(w + 4);
                ulonglong2 wc = *(const ulonglong2*)(w + 8);
                u64 wp[6] = {wa.x, wa.y, wb.x, wb.y, wc.x, wc.y};
                u64 xv[2] = {splat(xr[dx]), splat(xr[dx + 1])};
#pragma unroll
                for (int p = 0; p < 2; ++p)
#pragma unroll
                    for (int s = 0; s < 6; ++s) fma2(acc[p][s], xv[p], wp[s]);
            }
        }
#pragma unroll
        for (int s = 0; s < 6; ++s) {
            float re0, im0, re1, im1;
            upk2(acc[0][s], re0, im0);
            upk2(acc[1][s], re1, im1);
            float2 m = make_float2(sqrtf(re0*re0 + im0*im0), sqrtf(re1*re1 + im1*im1));
            *(float2*)(g_mag + mbase0 + (size_t)(g * 6 + s) * PLANE) = m;
        }
    }
#endif
}

// ---------------------------------------------------------------------------
// Kernel B: channel mix (FFMA2), bias dropped (cancels in instance norm)
// ---------------------------------------------------------------------------
static const int SMEM_MIX = CIN * 32 * 4;

__global__ __launch_bounds__(256, 2)
void mix_kernel(const float* __restrict__ w1) {
    extern __shared__ float w1s[];
    const int tid = threadIdx.x;
    for (int i = tid; i < CIN * 32; i += 256) {
        int j = i >> 5, o = i & 31;
        w1s[i] = w1[o * CIN + j];
    }
    __syncthreads();

    const int bb = blockIdx.y;
    const int q0 = blockIdx.x * 512 + tid * 2;
    const float* mp = g_mag + (size_t)bb * CIN * PLANE + q0;

    u64 acc[16][2];
#pragma unroll
    for (int op = 0; op < 16; ++op) { acc[op][0] = 0ull; acc[op][1] = 0ull; }

#pragma unroll 4
    for (int j = 0; j < CIN; ++j) {
        float2 m = *(const float2*)(mp + (size_t)j * PLANE);
        u64 mx = splat(m.x), my = splat(m.y);
        const ulonglong2* wrow = (const ulonglong2*)(w1s + j * 32);
#pragma unroll
        for (int q4 = 0; q4 < 8; ++q4) {
            ulonglong2 w2 = wrow[q4];
            fma2(acc[q4 * 2 + 0][0], mx, w2.x);
            fma2(acc[q4 * 2 + 0][1], my, w2.x);
            fma2(acc[q4 * 2 + 1][0], mx, w2.y);
            fma2(acc[q4 * 2 + 1][1], my, w2.y);
        }
    }
#pragma unroll
    for (int op = 0; op < 16; ++op) {
        float a0lo, a0hi, a1lo, a1hi;
        upk2(acc[op][0], a0lo, a0hi);
        upk2(acc[op][1], a1lo, a1hi);
        *(float2*)(g_z + (size_t)(bb * 32 + 2 * op)     * PLANE + q0) = make_float2(a0lo, a1lo);
        *(float2*)(g_z + (size_t)(bb * 32 + 2 * op + 1) * PLANE + q0) = make_float2(a0hi, a1hi);
    }
}

// ---------------------------------------------------------------------------
__global__ void stats_kernel() {
    const int plane = blockIdx.x;
    const float* zp = g_z + (size_t)plane * PLANE;
    const int tid = threadIdx.x;
    float s = 0.f, s2 = 0.f;
    for (int i = tid * 4; i < PLANE; i += 1024) {
        float4 v = *(const float4*)(zp + i);
        s  += v.x + v.y + v.z + v.w;
        s2 += v.x * v.x + v.y * v.y + v.z * v.z + v.w * v.w;
    }
    __shared__ float r1[256], r2[256];
    r1[tid] = s; r2[tid] = s2;
    __syncthreads();
    for (int st = 128; st > 0; st >>= 1) {
        if (tid < st) { r1[tid] += r1[tid + st]; r2[tid] += r2[tid + st]; }
        __syncthreads();
    }
    if (tid == 0) {
        float mean = r1[0] * (1.f / PLANE);
        float var  = r2[0] * (1.f / PLANE) - mean * mean;
        g_stats[plane * 2]     = mean;
        g_stats[plane * 2 + 1] = rsqrtf(var + 1e-5f);
    }
}

__global__ void norm_kernel(float* __restrict__ out) {
    __shared__ float s[32][33];
    const int plane = blockIdx.y;
    const int tile  = blockIdx.x;
    const int hb = (tile >> 2) * 32, wb = (tile & 3) * 32;
    const float mean = g_stats[plane * 2];
    const float rstd = g_stats[plane * 2 + 1];
    const float* zp = g_z + (size_t)plane * PLANE;
    float* op = out + (size_t)plane * PLANE;
    const int cc = threadIdx.x & 31;
    const int r0 = threadIdx.x >> 5;
#pragma unroll
    for (int k = 0; k < 4; ++k) {
        int rr = r0 + k * 8;
        s[rr][cc] = zp[(wb + rr) * HW + hb + cc];
    }
    __syncthreads();
#pragma unroll
    for (int k = 0; k < 4; ++k) {
        int rr = r0 + k * 8;
        op[(hb + rr) * HW + wb + cc] = (s[cc][rr] - mean) * rstd;
    }
}

// ---------------------------------------------------------------------------
extern "C" void kernel_launch(void* const* d_in, const int* in_sizes, int n_in,
                              void* d_out, int out_size) {
    const float* x       = (const float*)d_in[0];
    const float* filters = (const float*)d_in[1];
    const float* w1      = (const float*)d_in[2];
    float* out = (float*)d_out;

    cudaFuncSetAttribute(gabor_mma_kernel, cudaFuncAttributeMaxDynamicSharedMemorySize, SMEM_GABOR);
    cudaFuncSetAttribute(mix_kernel,       cudaFuncAttributeMaxDynamicSharedMemorySize, SMEM_MIX);

    gabor_mma_kernel<<<dim3(32, 128), 256, SMEM_GABOR>>>(x, filters);
    mix_kernel<<<dim3(32, 4), 256, SMEM_MIX>>>(w1);
    stats_kernel<<<128, 256>>>();
    norm_kernel<<<dim3(16, 128), 256>>>(out);
}

// round 10
// speedup vs baseline: 3.3512x; 1.0032x over previous
#include <cuda_runtime.h>
#include <cstdint>
#include <math.h>

#define KK     15
#define HW     128
#define PLANE  16384
#define CIN    768
#define NSO    24
#define NF     48          // filters (N dim)
#define RT     4           // output rows per CTA
#define ARING  10          // TMEM A-chunk ring slots (32 cols each)
#define NCHUNK 18          // RT + 14 input rows per CTA
#define NROUND 8           // ceil(KK/2) sync rounds, 2 dy each

// ---- smem layout (bytes) for tcgen05 path ----
#define SM_TMEM   0
#define SM_MBAR   64                 // 8 mbarriers x 8B
#define SM_B      1024               // 4 B-slots x 6144B (48 rows x 128B, SW128)
#define SLOT_BF   6144
#define SM_X      (SM_B + 4*SLOT_BF) // 25600: 18 x-rows x 128 floats
// tcgen05 path needs ~34816; fallback needs 53568. Launch with max.
#define SMEM_GABOR 53568

// TMEM columns: D tiles at r*48 (r=0..3, 192 cols); A ring at 192 + slot*32
#define TM_A0  192
#define TM_DSTRIDE 48

// idesc: dfmt=F32(1)<<4 | afmt=TF32(2)<<7 | bfmt=TF32(2)<<10 | (N/8)<<17 | (M/16)<<24
#define IDESC_TF32 ((1u<<4) | (2u<<7) | (2u<<10) | ((NF/8)<<17) | ((128/16)<<24))

#if defined(__CUDA_ARCH__) && (defined(__CUDA_ARCH_FEAT_SM103_ALL) || defined(__CUDA_ARCH_SPECIFIC__))
#define HAS_TCGEN05 1
#else
#define HAS_TCGEN05 0
#endif

typedef unsigned long long u64;

// Scratch (.bss)
__device__ float g_mag[(size_t)4 * CIN * PLANE];   // [b][c*24+so][y*128+x]
__device__ float g_z[(size_t)128 * PLANE];
__device__ float g_stats[256];

// ---------------- portable helpers ----------------
__device__ __forceinline__ u64 splat(float v) {
    u64 r; asm("mov.b64 %0, {%1,%1};" : "=l"(r) : "f"(v)); return r;
}
__device__ __forceinline__ void fma2(u64& d, u64 a, u64 b) {
    asm("fma.rn.f32x2 %0, %1, %2, %0;" : "+l"(d) : "l"(a), "l"(b));
}
__device__ __forceinline__ void upk2(u64 v, float& lo, float& hi) {
    asm("mov.b64 {%0,%1}, %2;" : "=f"(lo), "=f"(hi) : "l"(v));
}

#if HAS_TCGEN05
// ---------------- sm_103a-only helpers ----------------
__device__ __forceinline__ uint32_t smem_u32(const void* p) {
    uint32_t a;
    asm("{ .reg .u64 t; cvta.to.shared.u64 t, %1; cvt.u32.u64 %0, t; }" : "=r"(a) : "l"(p));
    return a;
}
__device__ __forceinline__ uint32_t elect1() {
    uint32_t p;
    asm volatile("{ .reg .pred p; elect.sync _|p, 0xFFFFFFFF; selp.b32 %0,1,0,p; }" : "=r"(p));
    return p;
}
__device__ __forceinline__ float tf32r(float v) {
    uint32_t r; asm("cvt.rna.tf32.f32 %0, %1;" : "=r"(r) : "f"(v));
    return __uint_as_float(r);
}
#define SWZ(o) ((o) ^ ((((uint32_t)(o)) >> 3) & 0x70))

static __device__ __forceinline__ uint64_t mkdesc(uint32_t addr) {
    const uint64_t base = (uint64_t(2) << 61) | (uint64_t(1) << 46)
                        | (uint64_t(64) << 32) | (uint64_t(1) << 16);  // SW128
    return base | ((uint64_t)(addr >> 4) & 0x3FFF);
}
__device__ __forceinline__ void tmem_alloc(uint32_t smem_addr, uint32_t ncols) {
    asm volatile("tcgen05.alloc.cta_group::1.sync.aligned.shared::cta.b32 [%0], %1;"
                 :: "r"(smem_addr), "r"(ncols) : "memory");
}
__device__ __forceinline__ void tmem_relinq() {
    asm volatile("tcgen05.relinquish_alloc_permit.cta_group::1.sync.aligned;");
}
__device__ __forceinline__ void tmem_dealloc(uint32_t tmem, uint32_t ncols) {
    asm volatile("tcgen05.dealloc.cta_group::1.sync.aligned.b32 %0, %1;" :: "r"(tmem), "r"(ncols));
}
__device__ __forceinline__ void mbar_init(uint32_t a, uint32_t cnt) {
    asm volatile("mbarrier.init.shared.b64 [%0], %1;" :: "r"(a), "r"(cnt) : "memory");
}
__device__ __forceinline__ void mbar_inval(uint32_t a) {
    asm volatile("mbarrier.inval.shared.b64 [%0];" :: "r"(a) : "memory");
}
__device__ __forceinline__ void mbar_wait(uint32_t a, uint32_t par) {
    uint32_t done;
    asm volatile("{ .reg .pred p; mbarrier.try_wait.parity.acquire.cta.shared::cta.b64 p, [%1], %2;"
                 " selp.b32 %0,1,0,p; }" : "=r"(done) : "r"(a), "r"(par) : "memory");
    if (!done) {
        asm volatile("{ .reg .pred P1; WL_%=: mbarrier.try_wait.parity.acquire.cta.shared::cta.b64 P1, [%0], %1, 0x989680;"
                     " @P1 bra.uni WD_%=; bra.uni WL_%=; WD_%=: }" :: "r"(a), "r"(par) : "memory");
    }
}
__device__ __forceinline__ void mma_commit(uint32_t mbar) {
    asm volatile("tcgen05.commit.cta_group::1.mbarrier::arrive::one.shared::cluster.b64 [%0];"
                 :: "r"(mbar) : "memory");
}
// TS form: A in TMEM, B via SMEM descriptor
__device__ __forceinline__ void mma_tf32_ts(uint32_t d, uint32_t a, uint64_t bd, uint32_t en) {
    asm volatile("{ .reg .pred p; setp.ne.u32 p, %4, 0;"
                 " tcgen05.mma.cta_group::1.kind::tf32 [%0], [%1], %2, %3, {%5,%5,%5,%5}, p; }"
                 :: "r"(d), "r"(a), "l"(bd), "r"(IDESC_TF32), "r"(en), "r"(0u) : "memory");
}
__device__ __forceinline__ void fence_async_shared() {
    asm volatile("fence.proxy.async.shared::cta;" ::: "memory");
}
__device__ __forceinline__ void tc_fence_before() {
    asm volatile("tcgen05.fence::before_thread_sync;" ::: "memory");
}
__device__ __forceinline__ void tc_fence_after() {
    asm volatile("tcgen05.fence::after_thread_sync;" ::: "memory");
}
__device__ __forceinline__ void tc_wait_st() {
    asm volatile("tcgen05.wait::st.sync.aligned;" ::: "memory");
}
__device__ __forceinline__ void tc_wait_ld() {
    asm volatile("tcgen05.wait::ld.sync.aligned;" ::: "memory");
}
__device__ __forceinline__ void sttm_x32(uint32_t a, const uint32_t* r) {
    asm volatile("tcgen05.st.sync.aligned.32x32b.x32.b32 [%0], "
        "{%1,%2,%3,%4,%5,%6,%7,%8,%9,%10,%11,%12,%13,%14,%15,%16,"
        "%17,%18,%19,%20,%21,%22,%23,%24,%25,%26,%27,%28,%29,%30,%31,%32};"
        :: "r"(a),
           "r"(r[0]),"r"(r[1]),"r"(r[2]),"r"(r[3]),"r"(r[4]),"r"(r[5]),"r"(r[6]),"r"(r[7]),
           "r"(r[8]),"r"(r[9]),"r"(r[10]),"r"(r[11]),"r"(r[12]),"r"(r[13]),"r"(r[14]),"r"(r[15]),
           "r"(r[16]),"r"(r[17]),"r"(r[18]),"r"(r[19]),"r"(r[20]),"r"(r[21]),"r"(r[22]),"r"(r[23]),
           "r"(r[24]),"r"(r[25]),"r"(r[26]),"r"(r[27]),"r"(r[28]),"r"(r[29]),"r"(r[30]),"r"(r[31])
        : "memory");
}
__device__ __forceinline__ void ldtm_x16(uint32_t* r, uint32_t a) {
    asm volatile("tcgen05.ld.sync.aligned.32x32b.x16.b32 "
        "{%0,%1,%2,%3,%4,%5,%6,%7,%8,%9,%10,%11,%12,%13,%14,%15}, [%16];"
        : "=r"(r[0]),"=r"(r[1]),"=r"(r[2]),"=r"(r[3]),"=r"(r[4]),"=r"(r[5]),"=r"(r[6]),"=r"(r[7]),
          "=r"(r[8]),"=r"(r[9]),"=r"(r[10]),"=r"(r[11]),"=r"(r[12]),"=r"(r[13]),"=r"(r[14]),"=r"(r[15])
        : "r"(a));
}

// im2col chunk builder (A split: cols 0-15 hi(tf32), 16-31 lo(tf32 of residual))
__device__ __forceinline__ void build_chunk(char* smem, uint32_t tmem_a, int ci, int wid, int lid) {
    const float* xr = (const float*)(smem + SM_X) + ci * HW;
    const int xpos = (wid << 5) + lid;
    uint32_t regs[32];
#pragma unroll
    for (int dx = 0; dx < 16; ++dx) {
        int sx = xpos + dx - 7;
        float v = (dx < 15 && sx >= 0 && sx < HW) ? xr[sx] : 0.f;
        float hi = tf32r(v);
        regs[dx]      = __float_as_uint(hi);
        regs[16 + dx] = __float_as_uint(tf32r(v - hi));
    }
    sttm_x32(tmem_a + ((uint32_t)wid << 21), regs);
}
// Filters for one dy into SMEM (SW128): cols 0-15 hi, 16-31 lo (lo unused by the
// 2-term MMA loop but kept identical to R9's builder to isolate the variable).
__device__ __forceinline__ void build_filt(char* smem, int boff, const float* __restrict__ filters,
                                           int dy, int t) {
    for (int i = t; i < NF * 32; i += 128) {
        int f = i >> 5, col = i & 31, dx = col & 15;
        float v = (dx < 15) ? filters[(f >> 1) * 450 + (f & 1) * 225 + dy * 15 + dx] : 0.f;
        float hi = tf32r(v);
        float val = (col >= 16) ? tf32r(v - hi) : hi;
        *(float*)(smem + boff + SWZ(f * 128 + col * 4)) = val;
    }
}
#endif  // HAS_TCGEN05

// ---------------------------------------------------------------------------
// Kernel A: Gabor conv + magnitude.
// sm_103a: tcgen05 tf32 TS-mode implicit GEMM.
// 2-term split: D = (Ahi + Alo) x Bhi  (A exact fp32, B rounded once to tf32),
// 2 dy per sync round (8 rounds), ring-10 A, D stride 48.
// grid (32 row-groups, 128 planes), 256 threads, occ 1
// ---------------------------------------------------------------------------
__global__ __launch_bounds__(256, 1)
void gabor_mma_kernel(const float* __restrict__ x, const float* __restrict__ filters) {
#if HAS_TCGEN05
    extern __shared__ char smem[];
    const uint32_t sb = smem_u32(smem);
    const int tid = threadIdx.x, wid = tid >> 5, lid = tid & 31;
    const int plane = blockIdx.y;
    const int y0 = blockIdx.x * RT;
    const int b = plane >> 5, c = plane & 31;

    if (wid == 0) tmem_alloc(sb + SM_TMEM, 512);
    if (tid == 0)
        for (int i = 0; i < NROUND; ++i) mbar_init(sb + SM_MBAR + i * 8, 1);

    // stage NCHUNK x-rows (zero-padded in y)
    const float* xp = x + (size_t)plane * PLANE;
    float* xs = (float*)(smem + SM_X);
    for (int i = tid; i < NCHUNK * HW; i += 256) {
        int rr = i >> 7, cc = i & 127;
        int gy = y0 + rr - 7;
        xs[i] = (gy >= 0 && gy < HW) ? xp[gy * HW + cc] : 0.f;
    }
    __syncthreads();
    uint32_t tmem;
    asm volatile("ld.shared.b32 %0, [%1];" : "=r"(tmem) : "r"(sb + SM_TMEM));
    if (wid == 0) tmem_relinq();

    // prebuild A chunks 0..4 into ring slots 0..4
    if (wid < 4) {
        for (int ci = 0; ci < 5; ++ci)
            build_chunk(smem, tmem + TM_A0 + (ci % ARING) * 32, ci, wid, lid);
        tc_wait_st();
    }

    for (int rd = 0; rd < NROUND; ++rd) {
        const int dy0 = rd * 2;
        if (rd >= 2) mbar_wait(sb + SM_MBAR + (rd - 2) * 8, 0);   // depth-2 rounds
        if (wid < 4) {
#pragma unroll
            for (int j = 0; j < 2; ++j) {
                int ci = dy0 + 5 + j;
                if (ci < NCHUNK)
                    build_chunk(smem, tmem + TM_A0 + (ci % ARING) * 32, ci, wid, lid);
            }
            tc_wait_st();
        } else {
#pragma unroll
            for (int j = 0; j < 2; ++j) {
                int dy = dy0 + j;
                if (dy < KK)
                    build_filt(smem, SM_B + ((rd & 1) * 2 + j) * SLOT_BF, filters, dy, tid - 128);
            }
        }
        tc_fence_before();
        fence_async_shared();
        __syncthreads();
        if (wid == 0) {
            tc_fence_after();
            if (elect1()) {
#pragma unroll
                for (int j = 0; j < 2; ++j) {
                    int dy = dy0 + j;
                    if (dy >= KK) break;
                    uint64_t bd = mkdesc(sb + SM_B + ((rd & 1) * 2 + j) * SLOT_BF);
#pragma unroll
                    for (int r = 0; r < RT; ++r) {
                        uint32_t a = tmem + TM_A0 + ((dy + r) % ARING) * 32;
                        uint32_t d = tmem + r * TM_DSTRIDE;
                        mma_tf32_ts(d, a + 0,  bd + 0, dy > 0);  // hi x Bhi, k0
                        mma_tf32_ts(d, a + 8,  bd + 2, 1);       // hi x Bhi, k1
                        mma_tf32_ts(d, a + 16, bd + 0, 1);       // lo x Bhi, k0
                        mma_tf32_ts(d, a + 24, bd + 2, 1);       // lo x Bhi, k1
                    }
                }
                mma_commit(sb + SM_MBAR + rd * 8);
            }
        }
    }
    mbar_wait(sb + SM_MBAR + (NROUND - 1) * 8, 0);
    tc_fence_after();

    // epilogue: warps 0-3 -> tiles 0,1 ; warps 4-7 -> tiles 2,3 ; sub = wid&3
    const int sub = wid & 3;
    const int xc = sub * 32 + lid;
    const size_t mbase = ((size_t)b * CIN + (size_t)c * NSO) * PLANE + xc;
#pragma unroll
    for (int rr = 0; rr < 2; ++rr) {
        const int r = (wid >> 2) * 2 + rr;
        uint32_t rg[48];
        ldtm_x16(rg,      tmem + r * TM_DSTRIDE);
        ldtm_x16(rg + 16, tmem + r * TM_DSTRIDE + 16);
        ldtm_x16(rg + 32, tmem + r * TM_DSTRIDE + 32);
        tc_wait_ld();
        const int y = y0 + r;
#pragma unroll
        for (int s = 0; s < NSO; ++s) {
            float re = __uint_as_float(rg[2 * s]);
            float im = __uint_as_float(rg[2 * s + 1]);
            g_mag[mbase + (size_t)s * PLANE + (size_t)y * HW] = sqrtf(re * re + im * im);
        }
    }
    __syncthreads();
    if (tid == 0)
        for (int i = 0; i < NROUND; ++i) mbar_inval(sb + SM_MBAR + i * 8);
    __syncthreads();
    if (wid == 0) tmem_dealloc(tmem, 512);

#else  // ---------------- scalar FFMA2 fallback (non-arch-specific pass) -----
    extern __shared__ float smf[];
    float* fs = smf;                        // [225][48]
    float* xs = smf + 225 * NF;             // [18][144]
    const int XW = 144;
    const int tid = threadIdx.x;
    const int plane = blockIdx.y;
    const int y0 = blockIdx.x * RT;
    const int b = plane >> 5, c = plane & 31;

    for (int i = tid; i < 225 * NF; i += 256) {
        int tap = i / NF, f = i - tap * NF;
        fs[i] = filters[(f >> 1) * 450 + (f & 1) * 225 + tap];
    }
    const float* xp = x + (size_t)plane * PLANE;
    for (int i = tid; i < NCHUNK * XW; i += 256) {
        int rr = i / XW, cc = i - rr * XW;
        int gy = y0 + rr - 7, gx = cc - 7;
        xs[i] = (gy >= 0 && gy < HW && gx >= 0 && gx < HW) ? xp[gy * HW + gx] : 0.f;
    }
    __syncthreads();

    const int x0 = (tid & 63) * 2;
    const int ry = tid >> 6;
    const size_t mbase0 = ((size_t)b * CIN + (size_t)c * NSO) * PLANE
                        + (size_t)(y0 + ry) * HW + x0;
    for (int g = 0; g < 4; ++g) {
        u64 acc[2][6];
#pragma unroll
        for (int p = 0; p < 2; ++p)
#pragma unroll
            for (int s = 0; s < 6; ++s) acc[p][s] = 0ull;
        for (int dy = 0; dy < KK; ++dy) {
            const float* xr = xs + (ry + dy) * XW + x0;
            const float* wr = fs + dy * KK * NF + g * 12;
#pragma unroll
            for (int dx = 0; dx < KK; ++dx) {
                const float* w = wr + dx * NF;
                ulonglong2 wa = *(const ulonglong2*)(w);
                ulonglong2 wb = *(const ulonglong2*)(w + 4);
                ulonglong2 wc = *(const ulonglong2*)(w + 8);
                u64 wp[6] = {wa.x, wa.y, wb.x, wb.y, wc.x, wc.y};
                u64 xv[2] = {splat(xr[dx]), splat(xr[dx + 1])};
#pragma unroll
                for (int p = 0; p < 2; ++p)
#pragma unroll
                    for (int s = 0; s < 6; ++s) fma2(acc[p][s], xv[p], wp[s]);
            }
        }
#pragma unroll
        for (int s = 0; s < 6; ++s) {
            float re0, im0, re1, im1;
            upk2(acc[0][s], re0, im0);
            upk2(acc[1][s], re1, im1);
            float2 m = make_float2(sqrtf(re0*re0 + im0*im0), sqrtf(re1*re1 + im1*im1));
            *(float2*)(g_mag + mbase0 + (size_t)(g * 6 + s) * PLANE) = m;
        }
    }
#endif
}

// ---------------------------------------------------------------------------
// Kernel B: channel mix (FFMA2), bias dropped (cancels in instance norm)
// ---------------------------------------------------------------------------
static const int SMEM_MIX = CIN * 32 * 4;

__global__ __launch_bounds__(256, 2)
void mix_kernel(const float* __restrict__ w1) {
    extern __shared__ float w1s[];
    const int tid = threadIdx.x;
    for (int i = tid; i < CIN * 32; i += 256) {
        int j = i >> 5, o = i & 31;
        w1s[i] = w1[o * CIN + j];
    }
    __syncthreads();

    const int bb = blockIdx.y;
    const int q0 = blockIdx.x * 512 + tid * 2;
    const float* mp = g_mag + (size_t)bb * CIN * PLANE + q0;

    u64 acc[16][2];
#pragma unroll
    for (int op = 0; op < 16; ++op) { acc[op][0] = 0ull; acc[op][1] = 0ull; }

#pragma unroll 4
    for (int j = 0; j < CIN; ++j) {
        float2 m = *(const float2*)(mp + (size_t)j * PLANE);
        u64 mx = splat(m.x), my = splat(m.y);
        const ulonglong2* wrow = (const ulonglong2*)(w1s + j * 32);
#pragma unroll
        for (int q4 = 0; q4 < 8; ++q4) {
            ulonglong2 w2 = wrow[q4];
            fma2(acc[q4 * 2 + 0][0], mx, w2.x);
            fma2(acc[q4 * 2 + 0][1], my, w2.x);
            fma2(acc[q4 * 2 + 1][0], mx, w2.y);
            fma2(acc[q4 * 2 + 1][1], my, w2.y);
        }
    }
#pragma unroll
    for (int op = 0; op < 16; ++op) {
        float a0lo, a0hi, a1lo, a1hi;
        upk2(acc[op][0], a0lo, a0hi);
        upk2(acc[op][1], a1lo, a1hi);
        *(float2*)(g_z + (size_t)(bb * 32 + 2 * op)     * PLANE + q0) = make_float2(a0lo, a1lo);
        *(float2*)(g_z + (size_t)(bb * 32 + 2 * op + 1) * PLANE + q0) = make_float2(a0hi, a1hi);
    }
}

// ---------------------------------------------------------------------------
__global__ void stats_kernel() {
    const int plane = blockIdx.x;
    const float* zp = g_z + (size_t)plane * PLANE;
    const int tid = threadIdx.x;
    float s = 0.f, s2 = 0.f;
    for (int i = tid * 4; i < PLANE; i += 1024) {
        float4 v = *(const float4*)(zp + i);
        s  += v.x + v.y + v.z + v.w;
        s2 += v.x * v.x + v.y * v.y + v.z * v.z + v.w * v.w;
    }
    __shared__ float r1[256], r2[256];
    r1[tid] = s; r2[tid] = s2;
    __syncthreads();
    for (int st = 128; st > 0; st >>= 1) {
        if (tid < st) { r1[tid] += r1[tid + st]; r2[tid] += r2[tid + st]; }
        __syncthreads();
    }
    if (tid == 0) {
        float mean = r1[0] * (1.f / PLANE);
        float var  = r2[0] * (1.f / PLANE) - mean * mean;
        g_stats[plane * 2]     = mean;
        g_stats[plane * 2 + 1] = rsqrtf(var + 1e-5f);
    }
}

__global__ void norm_kernel(float* __restrict__ out) {
    __shared__ float s[32][33];
    const int plane = blockIdx.y;
    const int tile  = blockIdx.x;
    const int hb = (tile >> 2) * 32, wb = (tile & 3) * 32;
    const float mean = g_stats[plane * 2];
    const float rstd = g_stats[plane * 2 + 1];
    const float* zp = g_z + (size_t)plane * PLANE;
    float* op = out + (size_t)plane * PLANE;
    const int cc = threadIdx.x & 31;
    const int r0 = threadIdx.x >> 5;
#pragma unroll
    for (int k = 0; k < 4; ++k) {
        int rr = r0 + k * 8;
        s[rr][cc] = zp[(wb + rr) * HW + hb + cc];
    }
    __syncthreads();
#pragma unroll
    for (int k = 0; k < 4; ++k) {
        int rr = r0 + k * 8;
        op[(hb + rr) * HW + wb + cc] = (s[cc][rr] - mean) * rstd;
    }
}

// ---------------------------------------------------------------------------
extern "C" void kernel_launch(void* const* d_in, const int* in_sizes, int n_in,
                              void* d_out, int out_size) {
    const float* x       = (const float*)d_in[0];
    const float* filters = (const float*)d_in[1];
    const float* w1      = (const float*)d_in[2];
    float* out = (float*)d_out;

    cudaFuncSetAttribute(gabor_mma_kernel, cudaFuncAttributeMaxDynamicSharedMemorySize, SMEM_GABOR);
    cudaFuncSetAttribute(mix_kernel,       cudaFuncAttributeMaxDynamicSharedMemorySize, SMEM_MIX);

    gabor_mma_kernel<<<dim3(32, 128), 256, SMEM_GABOR>>>(x, filters);
    mix_kernel<<<dim3(32, 4), 256, SMEM_MIX>>>(w1);
    stats_kernel<<<128, 256>>>();
    norm_kernel<<<dim3(16, 128), 256>>>(out);
}

// round 11
// speedup vs baseline: 3.7992x; 1.1337x over previous
#include <cuda_runtime.h>
#include <cstdint>
#include <math.h>

#define KK     15
#define HW     128
#define PLANE  16384
#define CIN    768
#define NSO    24
#define NF     48          // filters (N dim)
#define RT     4           // output rows per CTA
#define ARING  20          // TMEM A-chunk ring slots (16 cols each) - never reused
#define NCHUNK 18          // RT + 14 input rows per CTA
#define NROUND 8           // 2 dy per sync round
#define DEPTH  4           // pipeline depth in rounds

// ---- smem layout (bytes) for tcgen05 path ----
#define SM_TMEM   0
#define SM_MBAR   64                 // 8 mbarriers x 8B
#define SM_B      1024               // 8 B-slots x 6144B (48 rows x 128B, SW128)
#define SLOT_BF   6144
#define SM_X      (SM_B + 8*SLOT_BF) // 50176: 18 x-rows x 128 floats
// tcgen05 path needs 59392; fallback needs 53568.
#define SMEM_GABOR 59520

// TMEM columns: D tiles at r*48 (r=0..3, 192); A ring at 192 + slot*16 (320)
#define TM_A0  192
#define TM_DSTRIDE 48

// idesc: dfmt=F32(1)<<4 | afmt=TF32(2)<<7 | bfmt=TF32(2)<<10 | (N/8)<<17 | (M/16)<<24
#define IDESC_TF32 ((1u<<4) | (2u<<7) | (2u<<10) | ((NF/8)<<17) | ((128/16)<<24))

#if defined(__CUDA_ARCH__) && (defined(__CUDA_ARCH_FEAT_SM103_ALL) || defined(__CUDA_ARCH_SPECIFIC__))
#define HAS_TCGEN05 1
#else
#define HAS_TCGEN05 0
#endif

typedef unsigned long long u64;

// Scratch (.bss)
__device__ float g_mag[(size_t)4 * CIN * PLANE];   // [b][c*24+so][y*128+x]
__device__ float g_z[(size_t)128 * PLANE];
__device__ float g_stats[256];

// ---------------- portable helpers ----------------
__device__ __forceinline__ u64 splat(float v) {
    u64 r; asm("mov.b64 %0, {%1,%1};" : "=l"(r) : "f"(v)); return r;
}
__device__ __forceinline__ void fma2(u64& d, u64 a, u64 b) {
    asm("fma.rn.f32x2 %0, %1, %2, %0;" : "+l"(d) : "l"(a), "l"(b));
}
__device__ __forceinline__ void upk2(u64 v, float& lo, float& hi) {
    asm("mov.b64 {%0,%1}, %2;" : "=f"(lo), "=f"(hi) : "l"(v));
}

#if HAS_TCGEN05
// ---------------- sm_103a-only helpers ----------------
__device__ __forceinline__ uint32_t smem_u32(const void* p) {
    uint32_t a;
    asm("{ .reg .u64 t; cvta.to.shared.u64 t, %1; cvt.u32.u64 %0, t; }" : "=r"(a) : "l"(p));
    return a;
}
__device__ __forceinline__ uint32_t elect1() {
    uint32_t p;
    asm volatile("{ .reg .pred p; elect.sync _|p, 0xFFFFFFFF; selp.b32 %0,1,0,p; }" : "=r"(p));
    return p;
}
__device__ __forceinline__ float tf32r(float v) {
    uint32_t r; asm("cvt.rna.tf32.f32 %0, %1;" : "=r"(r) : "f"(v));
    return __uint_as_float(r);
}
#define SWZ(o) ((o) ^ ((((uint32_t)(o)) >> 3) & 0x70))

static __device__ __forceinline__ uint64_t mkdesc(uint32_t addr) {
    const uint64_t base = (uint64_t(2) << 61) | (uint64_t(1) << 46)
                        | (uint64_t(64) << 32) | (uint64_t(1) << 16);  // SW128
    return base | ((uint64_t)(addr >> 4) & 0x3FFF);
}
__device__ __forceinline__ void tmem_alloc(uint32_t smem_addr, uint32_t ncols) {
    asm volatile("tcgen05.alloc.cta_group::1.sync.aligned.shared::cta.b32 [%0], %1;"
                 :: "r"(smem_addr), "r"(ncols) : "memory");
}
__device__ __forceinline__ void tmem_relinq() {
    asm volatile("tcgen05.relinquish_alloc_permit.cta_group::1.sync.aligned;");
}
__device__ __forceinline__ void tmem_dealloc(uint32_t tmem, uint32_t ncols) {
    asm volatile("tcgen05.dealloc.cta_group::1.sync.aligned.b32 %0, %1;" :: "r"(tmem), "r"(ncols));
}
__device__ __forceinline__ void mbar_init(uint32_t a, uint32_t cnt) {
    asm volatile("mbarrier.init.shared.b64 [%0], %1;" :: "r"(a), "r"(cnt) : "memory");
}
__device__ __forceinline__ void mbar_inval(uint32_t a) {
    asm volatile("mbarrier.inval.shared.b64 [%0];" :: "r"(a) : "memory");
}
__device__ __forceinline__ void mbar_wait(uint32_t a, uint32_t par) {
    uint32_t done;
    asm volatile("{ .reg .pred p; mbarrier.try_wait.parity.acquire.cta.shared::cta.b64 p, [%1], %2;"
                 " selp.b32 %0,1,0,p; }" : "=r"(done) : "r"(a), "r"(par) : "memory");
    if (!done) {
        asm volatile("{ .reg .pred P1; WL_%=: mbarrier.try_wait.parity.acquire.cta.shared::cta.b64 P1, [%0], %1, 0x989680;"
                     " @P1 bra.uni WD_%=; bra.uni WL_%=; WD_%=: }" :: "r"(a), "r"(par) : "memory");
    }
}
__device__ __forceinline__ void mma_commit(uint32_t mbar) {
    asm volatile("tcgen05.commit.cta_group::1.mbarrier::arrive::one.shared::cluster.b64 [%0];"
                 :: "r"(mbar) : "memory");
}
// TS form: A in TMEM, B via SMEM descriptor
__device__ __forceinline__ void mma_tf32_ts(uint32_t d, uint32_t a, uint64_t bd, uint32_t en) {
    asm volatile("{ .reg .pred p; setp.ne.u32 p, %4, 0;"
                 " tcgen05.mma.cta_group::1.kind::tf32 [%0], [%1], %2, %3, {%5,%5,%5,%5}, p; }"
                 :: "r"(d), "r"(a), "l"(bd), "r"(IDESC_TF32), "r"(en), "r"(0u) : "memory");
}
__device__ __forceinline__ void fence_async_shared() {
    asm volatile("fence.proxy.async.shared::cta;" ::: "memory");
}
__device__ __forceinline__ void tc_fence_before() {
    asm volatile("tcgen05.fence::before_thread_sync;" ::: "memory");
}
__device__ __forceinline__ void tc_fence_after() {
    asm volatile("tcgen05.fence::after_thread_sync;" ::: "memory");
}
__device__ __forceinline__ void tc_wait_st() {
    asm volatile("tcgen05.wait::st.sync.aligned;" ::: "memory");
}
__device__ __forceinline__ void tc_wait_ld() {
    asm volatile("tcgen05.wait::ld.sync.aligned;" ::: "memory");
}
__device__ __forceinline__ void sttm_x16(uint32_t a, const uint32_t* r) {
    asm volatile("tcgen05.st.sync.aligned.32x32b.x16.b32 [%0], "
        "{%1,%2,%3,%4,%5,%6,%7,%8,%9,%10,%11,%12,%13,%14,%15,%16};"
        :: "r"(a),
           "r"(r[0]),"r"(r[1]),"r"(r[2]),"r"(r[3]),"r"(r[4]),"r"(r[5]),"r"(r[6]),"r"(r[7]),
           "r"(r[8]),"r"(r[9]),"r"(r[10]),"r"(r[11]),"r"(r[12]),"r"(r[13]),"r"(r[14]),"r"(r[15])
        : "memory");
}
__device__ __forceinline__ void ldtm_x16(uint32_t* r, uint32_t a) {
    asm volatile("tcgen05.ld.sync.aligned.32x32b.x16.b32 "
        "{%0,%1,%2,%3,%4,%5,%6,%7,%8,%9,%10,%11,%12,%13,%14,%15}, [%16];"
        : "=r"(r[0]),"=r"(r[1]),"=r"(r[2]),"=r"(r[3]),"=r"(r[4]),"=r"(r[5]),"=r"(r[6]),"=r"(r[7]),
          "=r"(r[8]),"=r"(r[9]),"=r"(r[10]),"=r"(r[11]),"=r"(r[12]),"=r"(r[13]),"=r"(r[14]),"=r"(r[15])
        : "r"(a));
}

// im2col chunk builder: A rounded once to tf32 (hi only), 16 cols per chunk
__device__ __forceinline__ void build_chunk(char* smem, uint32_t tmem_a, int ci, int wid, int lid) {
    const float* xr = (const float*)(smem + SM_X) + ci * HW;
    const int xpos = (wid << 5) + lid;
    uint32_t regs[16];
#pragma unroll
    for (int dx = 0; dx < 16; ++dx) {
        int sx = xpos + dx - 7;
        float v = (dx < 15 && sx >= 0 && sx < HW) ? xr[sx] : 0.f;
        regs[dx] = __float_as_uint(tf32r(v));
    }
    sttm_x16(tmem_a + ((uint32_t)wid << 21), regs);
}
// Filters for one dy into SMEM (SW128): cols 0-15 hi(tf32), 16-31 lo(residual tf32)
__device__ __forceinline__ void build_filt(char* smem, int boff, const float* __restrict__ filters,
                                           int dy, int t) {
    for (int i = t; i < NF * 32; i += 128) {
        int f = i >> 5, col = i & 31, dx = col & 15;
        float v = (dx < 15) ? filters[(f >> 1) * 450 + (f & 1) * 225 + dy * 15 + dx] : 0.f;
        float hi = tf32r(v);
        float val = (col >= 16) ? tf32r(v - hi) : hi;
        *(float*)(smem + boff + SWZ(f * 128 + col * 4)) = val;
    }
}
#endif  // HAS_TCGEN05

// ---------------------------------------------------------------------------
// Kernel A: Gabor conv + magnitude.
// sm_103a: tcgen05 tf32 TS-mode implicit GEMM.
// 2-term split: D = Ahi x (Bhi + Blo)  (A rounded once, B exact fp32),
// 2 dy/round (8 rounds), DEPTH-4 pipeline, A ring never reused, 8 B slots.
// grid (32 row-groups, 128 planes), 256 threads, occ 1
// ---------------------------------------------------------------------------
__global__ __launch_bounds__(256, 1)
void gabor_mma_kernel(const float* __restrict__ x, const float* __restrict__ filters) {
#if HAS_TCGEN05
    extern __shared__ char smem[];
    const uint32_t sb = smem_u32(smem);
    const int tid = threadIdx.x, wid = tid >> 5, lid = tid & 31;
    const int plane = blockIdx.y;
    const int y0 = blockIdx.x * RT;
    const int b = plane >> 5, c = plane & 31;

    // stage x + mbar init BEFORE tmem_alloc: next resident CTA overlaps this
    // with its blocked alloc.
    const float* xp = x + (size_t)plane * PLANE;
    float* xs = (float*)(smem + SM_X);
    for (int i = tid; i < NCHUNK * HW; i += 256) {
        int rr = i >> 7, cc = i & 127;
        int gy = y0 + rr - 7;
        xs[i] = (gy >= 0 && gy < HW) ? xp[gy * HW + cc] : 0.f;
    }
    if (tid == 0)
        for (int i = 0; i < NROUND; ++i) mbar_init(sb + SM_MBAR + i * 8, 1);
    __syncthreads();

    if (wid == 0) tmem_alloc(sb + SM_TMEM, 512);
    __syncthreads();
    uint32_t tmem;
    asm volatile("ld.shared.b32 %0, [%1];" : "=r"(tmem) : "r"(sb + SM_TMEM));
    if (wid == 0) tmem_relinq();

    // prebuild A chunks 0..4 (round 0 window)
    if (wid < 4) {
        for (int ci = 0; ci < 5; ++ci)
            build_chunk(smem, tmem + TM_A0 + ci * 16, ci, wid, lid);
        tc_wait_st();
    }

    for (int rd = 0; rd < NROUND; ++rd) {
        const int dy0 = rd * 2;
        if (rd >= DEPTH) mbar_wait(sb + SM_MBAR + (rd - DEPTH) * 8, 0);
        if (wid < 4) {
            // build A chunks for the next round's window (slots never reused)
#pragma unroll
            for (int j = 0; j < 2; ++j) {
                int ci = dy0 + 5 + j;
                if (ci < NCHUNK)
                    build_chunk(smem, tmem + TM_A0 + ci * 16, ci, wid, lid);
            }
            tc_wait_st();
        } else {
            // B slots (2rd+j)%8: reuse at rd+4 guarded by the wait(rd-4)
#pragma unroll
            for (int j = 0; j < 2; ++j) {
                int dy = dy0 + j;
                if (dy < KK)
                    build_filt(smem, SM_B + ((dy0 + j) & 7) * SLOT_BF, filters, dy, tid - 128);
            }
        }
        tc_fence_before();
        fence_async_shared();
        __syncthreads();
        if (wid == 0) {
            tc_fence_after();
            if (elect1()) {
#pragma unroll
                for (int j = 0; j < 2; ++j) {
                    int dy = dy0 + j;
                    if (dy >= KK) break;
                    uint64_t bd = mkdesc(sb + SM_B + ((dy0 + j) & 7) * SLOT_BF);
#pragma unroll
                    for (int r = 0; r < RT; ++r) {
                        uint32_t a = tmem + TM_A0 + (dy + r) * 16;
                        uint32_t d = tmem + r * TM_DSTRIDE;
                        mma_tf32_ts(d, a + 0, bd + 0, dy > 0);  // Ahi x Bhi, k0
                        mma_tf32_ts(d, a + 8, bd + 2, 1);       // Ahi x Bhi, k1
                        mma_tf32_ts(d, a + 0, bd + 4, 1);       // Ahi x Blo, k0
                        mma_tf32_ts(d, a + 8, bd + 6, 1);       // Ahi x Blo, k1
                    }
                }
                mma_commit(sb + SM_MBAR + rd * 8);
            }
        }
    }
    mbar_wait(sb + SM_MBAR + (NROUND - 1) * 8, 0);
    tc_fence_after();

    // epilogue: warps 0-3 -> tiles 0,1 ; warps 4-7 -> tiles 2,3 ; sub = wid&3
    const int sub = wid & 3;
    const int xc = sub * 32 + lid;
    const size_t mbase = ((size_t)b * CIN + (size_t)c * NSO) * PLANE + xc;
#pragma unroll
    for (int rr = 0; rr < 2; ++rr) {
        const int r = (wid >> 2) * 2 + rr;
        uint32_t rg[48];
        ldtm_x16(rg,      tmem + r * TM_DSTRIDE);
        ldtm_x16(rg + 16, tmem + r * TM_DSTRIDE + 16);
        ldtm_x16(rg + 32, tmem + r * TM_DSTRIDE + 32);
        tc_wait_ld();
        const int y = y0 + r;
#pragma unroll
        for (int s = 0; s < NSO; ++s) {
            float re = __uint_as_float(rg[2 * s]);
            float im = __uint_as_float(rg[2 * s + 1]);
            g_mag[mbase + (size_t)s * PLANE + (size_t)y * HW] = sqrtf(re * re + im * im);
        }
    }
    __syncthreads();
    if (tid == 0)
        for (int i = 0; i < NROUND; ++i) mbar_inval(sb + SM_MBAR + i * 8);
    __syncthreads();
    if (wid == 0) tmem_dealloc(tmem, 512);

#else  // ---------------- scalar FFMA2 fallback (non-arch-specific pass) -----
    extern __shared__ float smf[];
    float* fs = smf;                        // [225][48]
    float* xs = smf + 225 * NF;             // [18][144]
    const int XW = 144;
    const int tid = threadIdx.x;
    const int plane = blockIdx.y;
    const int y0 = blockIdx.x * RT;
    const int b = plane >> 5, c = plane & 31;

    for (int i = tid; i < 225 * NF; i += 256) {
        int tap = i / NF, f = i - tap * NF;
        fs[i] = filters[(f >> 1) * 450 + (f & 1) * 225 + tap];
    }
    const float* xp = x + (size_t)plane * PLANE;
    for (int i = tid; i < NCHUNK * XW; i += 256) {
        int rr = i / XW, cc = i - rr * XW;
        int gy = y0 + rr - 7, gx = cc - 7;
        xs[i] = (gy >= 0 && gy < HW && gx >= 0 && gx < HW) ? xp[gy * HW + gx] : 0.f;
    }
    __syncthreads();

    const int x0 = (tid & 63) * 2;
    const int ry = tid >> 6;
    const size_t mbase0 = ((size_t)b * CIN + (size_t)c * NSO) * PLANE
                        + (size_t)(y0 + ry) * HW + x0;
    for (int g = 0; g < 4; ++g) {
        u64 acc[2][6];
#pragma unroll
        for (int p = 0; p < 2; ++p)
#pragma unroll
            for (int s = 0; s < 6; ++s) acc[p][s] = 0ull;
        for (int dy = 0; dy < KK; ++dy) {
            const float* xr = xs + (ry + dy) * XW + x0;
            const float* wr = fs + dy * KK * NF + g * 12;
#pragma unroll
            for (int dx = 0; dx < KK; ++dx) {
                const float* w = wr + dx * NF;
                ulonglong2 wa = *(const ulonglong2*)(w);
                ulonglong2 wb = *(const ulonglong2*)(w + 4);
                ulonglong2 wc = *(const ulonglong2*)(w + 8);
                u64 wp[6] = {wa.x, wa.y, wb.x, wb.y, wc.x, wc.y};
                u64 xv[2] = {splat(xr[dx]), splat(xr[dx + 1])};
#pragma unroll
                for (int p = 0; p < 2; ++p)
#pragma unroll
                    for (int s = 0; s < 6; ++s) fma2(acc[p][s], xv[p], wp[s]);
            }
        }
#pragma unroll
        for (int s = 0; s < 6; ++s) {
            float re0, im0, re1, im1;
            upk2(acc[0][s], re0, im0);
            upk2(acc[1][s], re1, im1);
            float2 m = make_float2(sqrtf(re0*re0 + im0*im0), sqrtf(re1*re1 + im1*im1));
            *(float2*)(g_mag + mbase0 + (size_t)(g * 6 + s) * PLANE) = m;
        }
    }
#endif
}

// ---------------------------------------------------------------------------
// Kernel B: channel mix (FFMA2), bias dropped (cancels in instance norm)
// ---------------------------------------------------------------------------
static const int SMEM_MIX = CIN * 32 * 4;

__global__ __launch_bounds__(256, 2)
void mix_kernel(const float* __restrict__ w1) {
    extern __shared__ float w1s[];
    const int tid = threadIdx.x;
    for (int i = tid; i < CIN * 32; i += 256) {
        int j = i >> 5, o = i & 31;
        w1s[i] = w1[o * CIN + j];
    }
    __syncthreads();

    const int bb = blockIdx.y;
    const int q0 = blockIdx.x * 512 + tid * 2;
    const float* mp = g_mag + (size_t)bb * CIN * PLANE + q0;

    u64 acc[16][2];
#pragma unroll
    for (int op = 0; op < 16; ++op) { acc[op][0] = 0ull; acc[op][1] = 0ull; }

#pragma unroll 4
    for (int j = 0; j < CIN; ++j) {
        float2 m = *(const float2*)(mp + (size_t)j * PLANE);
        u64 mx = splat(m.x), my = splat(m.y);
        const ulonglong2* wrow = (const ulonglong2*)(w1s + j * 32);
#pragma unroll
        for (int q4 = 0; q4 < 8; ++q4) {
            ulonglong2 w2 = wrow[q4];
            fma2(acc[q4 * 2 + 0][0], mx, w2.x);
            fma2(acc[q4 * 2 + 0][1], my, w2.x);
            fma2(acc[q4 * 2 + 1][0], mx, w2.y);
            fma2(acc[q4 * 2 + 1][1], my, w2.y);
        }
    }
#pragma unroll
    for (int op = 0; op < 16; ++op) {
        float a0lo, a0hi, a1lo, a1hi;
        upk2(acc[op][0], a0lo, a0hi);
        upk2(acc[op][1], a1lo, a1hi);
        *(float2*)(g_z + (size_t)(bb * 32 + 2 * op)     * PLANE + q0) = make_float2(a0lo, a1lo);
        *(float2*)(g_z + (size_t)(bb * 32 + 2 * op + 1) * PLANE + q0) = make_float2(a0hi, a1hi);
    }
}

// ---------------------------------------------------------------------------
__global__ void stats_kernel() {
    const int plane = blockIdx.x;
    const float* zp = g_z + (size_t)plane * PLANE;
    const int tid = threadIdx.x;
    float s = 0.f, s2 = 0.f;
    for (int i = tid * 4; i < PLANE; i += 1024) {
        float4 v = *(const float4*)(zp + i);
        s  += v.x + v.y + v.z + v.w;
        s2 += v.x * v.x + v.y * v.y + v.z * v.z + v.w * v.w;
    }
    __shared__ float r1[256], r2[256];
    r1[tid] = s; r2[tid] = s2;
    __syncthreads();
    for (int st = 128; st > 0; st >>= 1) {
        if (tid < st) { r1[tid] += r1[tid + st]; r2[tid] += r2[tid + st]; }
        __syncthreads();
    }
    if (tid == 0) {
        float mean = r1[0] * (1.f / PLANE);
        float var  = r2[0] * (1.f / PLANE) - mean * mean;
        g_stats[plane * 2]     = mean;
        g_stats[plane * 2 + 1] = rsqrtf(var + 1e-5f);
    }
}

__global__ void norm_kernel(float* __restrict__ out) {
    __shared__ float s[32][33];
    const int plane = blockIdx.y;
    const int tile  = blockIdx.x;
    const int hb = (tile >> 2) * 32, wb = (tile & 3) * 32;
    const float mean = g_stats[plane * 2];
    const float rstd = g_stats[plane * 2 + 1];
    const float* zp = g_z + (size_t)plane * PLANE;
    float* op = out + (size_t)plane * PLANE;
    const int cc = threadIdx.x & 31;
    const int r0 = threadIdx.x >> 5;
#pragma unroll
    for (int k = 0; k < 4; ++k) {
        int rr = r0 + k * 8;
        s[rr][cc] = zp[(wb + rr) * HW + hb + cc];
    }
    __syncthreads();
#pragma unroll
    for (int k = 0; k < 4; ++k) {
        int rr = r0 + k * 8;
        op[(hb + rr) * HW + wb + cc] = (s[cc][rr] - mean) * rstd;
    }
}

// ---------------------------------------------------------------------------
extern "C" void kernel_launch(void* const* d_in, const int* in_sizes, int n_in,
                              void* d_out, int out_size) {
    const float* x       = (const float*)d_in[0];
    const float* filters = (const float*)d_in[1];
    const float* w1      = (const float*)d_in[2];
    float* out = (float*)d_out;

    cudaFuncSetAttribute(gabor_mma_kernel, cudaFuncAttributeMaxDynamicSharedMemorySize, SMEM_GABOR);
    cudaFuncSetAttribute(mix_kernel,       cudaFuncAttributeMaxDynamicSharedMemorySize, SMEM_MIX);

    gabor_mma_kernel<<<dim3(32, 128), 256, SMEM_GABOR>>>(x, filters);
    mix_kernel<<<dim3(32, 4), 256, SMEM_MIX>>>(w1);
    stats_kernel<<<128, 256>>>();
    norm_kernel<<<dim3(16, 128), 256>>>(out);
}

// round 12
// speedup vs baseline: 3.8476x; 1.0127x over previous
#include <cuda_runtime.h>
#include <cstdint>
#include <math.h>

#define KK     15
#define HW     128
#define PLANE  16384
#define CIN    768
#define NSO    24
#define NF     48          // filters (N dim)
#define RT     4           // output rows per CTA
#define NCHUNK 18          // RT + 14 input rows per CTA

// ---- smem layout (bytes) for tcgen05 path ----
#define SM_TMEM   0
#define SM_MBAR   64                  // 1 mbarrier
#define SM_B      1024                // 15 B-slots x 6144B (48 rows x 128B, SW128)
#define SLOT_BF   6144
#define SM_X      (SM_B + 15*SLOT_BF) // 93184: 18 x-rows x 128 floats
#define SMEM_GABOR 102528             // 93184 + 9216 + pad (fallback needs 53568)

// TMEM columns: D tiles at r*48 (r=0..3, 192); A chunks at 192 + ci*16 (288)
#define TM_A0  192
#define TM_DSTRIDE 48

// idesc: dfmt=F32(1)<<4 | afmt=TF32(2)<<7 | bfmt=TF32(2)<<10 | (N/8)<<17 | (M/16)<<24
#define IDESC_TF32 ((1u<<4) | (2u<<7) | (2u<<10) | ((NF/8)<<17) | ((128/16)<<24))

#if defined(__CUDA_ARCH__) && (defined(__CUDA_ARCH_FEAT_SM103_ALL) || defined(__CUDA_ARCH_SPECIFIC__))
#define HAS_TCGEN05 1
#else
#define HAS_TCGEN05 0
#endif

typedef unsigned long long u64;

// Scratch (.bss)
__device__ float g_mag[(size_t)4 * CIN * PLANE];   // [b][c*24+so][y*128+x]
__device__ float g_z[(size_t)128 * PLANE];
__device__ float g_stats[256];

// ---------------- portable helpers ----------------
__device__ __forceinline__ u64 splat(float v) {
    u64 r; asm("mov.b64 %0, {%1,%1};" : "=l"(r) : "f"(v)); return r;
}
__device__ __forceinline__ void fma2(u64& d, u64 a, u64 b) {
    asm("fma.rn.f32x2 %0, %1, %2, %0;" : "+l"(d) : "l"(a), "l"(b));
}
__device__ __forceinline__ void upk2(u64 v, float& lo, float& hi) {
    asm("mov.b64 {%0,%1}, %2;" : "=f"(lo), "=f"(hi) : "l"(v));
}

#if HAS_TCGEN05
// ---------------- sm_103a-only helpers ----------------
__device__ __forceinline__ uint32_t smem_u32(const void* p) {
    uint32_t a;
    asm("{ .reg .u64 t; cvta.to.shared.u64 t, %1; cvt.u32.u64 %0, t; }" : "=r"(a) : "l"(p));
    return a;
}
__device__ __forceinline__ uint32_t elect1() {
    uint32_t p;
    asm volatile("{ .reg .pred p; elect.sync _|p, 0xFFFFFFFF; selp.b32 %0,1,0,p; }" : "=r"(p));
    return p;
}
__device__ __forceinline__ float tf32r(float v) {
    uint32_t r; asm("cvt.rna.tf32.f32 %0, %1;" : "=r"(r) : "f"(v));
    return __uint_as_float(r);
}
#define SWZ(o) ((o) ^ ((((uint32_t)(o)) >> 3) & 0x70))

static __device__ __forceinline__ uint64_t mkdesc(uint32_t addr) {
    const uint64_t base = (uint64_t(2) << 61) | (uint64_t(1) << 46)
                        | (uint64_t(64) << 32) | (uint64_t(1) << 16);  // SW128
    return base | ((uint64_t)(addr >> 4) & 0x3FFF);
}
__device__ __forceinline__ void tmem_alloc(uint32_t smem_addr, uint32_t ncols) {
    asm volatile("tcgen05.alloc.cta_group::1.sync.aligned.shared::cta.b32 [%0], %1;"
                 :: "r"(smem_addr), "r"(ncols) : "memory");
}
__device__ __forceinline__ void tmem_relinq() {
    asm volatile("tcgen05.relinquish_alloc_permit.cta_group::1.sync.aligned;");
}
__device__ __forceinline__ void tmem_dealloc(uint32_t tmem, uint32_t ncols) {
    asm volatile("tcgen05.dealloc.cta_group::1.sync.aligned.b32 %0, %1;" :: "r"(tmem), "r"(ncols));
}
__device__ __forceinline__ void mbar_init(uint32_t a, uint32_t cnt) {
    asm volatile("mbarrier.init.shared.b64 [%0], %1;" :: "r"(a), "r"(cnt) : "memory");
}
__device__ __forceinline__ void mbar_inval(uint32_t a) {
    asm volatile("mbarrier.inval.shared.b64 [%0];" :: "r"(a) : "memory");
}
__device__ __forceinline__ void mbar_wait(uint32_t a, uint32_t par) {
    uint32_t done;
    asm volatile("{ .reg .pred p; mbarrier.try_wait.parity.acquire.cta.shared::cta.b64 p, [%1], %2;"
                 " selp.b32 %0,1,0,p; }" : "=r"(done) : "r"(a), "r"(par) : "memory");
    if (!done) {
        asm volatile("{ .reg .pred P1; WL_%=: mbarrier.try_wait.parity.acquire.cta.shared::cta.b64 P1, [%0], %1, 0x989680;"
                     " @P1 bra.uni WD_%=; bra.uni WL_%=; WD_%=: }" :: "r"(a), "r"(par) : "memory");
    }
}
__device__ __forceinline__ void mma_commit(uint32_t mbar) {
    asm volatile("tcgen05.commit.cta_group::1.mbarrier::arrive::one.shared::cluster.b64 [%0];"
                 :: "r"(mbar) : "memory");
}
// TS form: A in TMEM, B via SMEM descriptor
__device__ __forceinline__ void mma_tf32_ts(uint32_t d, uint32_t a, uint64_t bd, uint32_t en) {
    asm volatile("{ .reg .pred p; setp.ne.u32 p, %4, 0;"
                 " tcgen05.mma.cta_group::1.kind::tf32 [%0], [%1], %2, %3, {%5,%5,%5,%5}, p; }"
                 :: "r"(d), "r"(a), "l"(bd), "r"(IDESC_TF32), "r"(en), "r"(0u) : "memory");
}
__device__ __forceinline__ void fence_async_shared() {
    asm volatile("fence.proxy.async.shared::cta;" ::: "memory");
}
__device__ __forceinline__ void tc_fence_before() {
    asm volatile("tcgen05.fence::before_thread_sync;" ::: "memory");
}
__device__ __forceinline__ void tc_fence_after() {
    asm volatile("tcgen05.fence::after_thread_sync;" ::: "memory");
}
__device__ __forceinline__ void tc_wait_st() {
    asm volatile("tcgen05.wait::st.sync.aligned;" ::: "memory");
}
__device__ __forceinline__ void tc_wait_ld() {
    asm volatile("tcgen05.wait::ld.sync.aligned;" ::: "memory");
}
__device__ __forceinline__ void sttm_x16(uint32_t a, const uint32_t* r) {
    asm volatile("tcgen05.st.sync.aligned.32x32b.x16.b32 [%0], "
        "{%1,%2,%3,%4,%5,%6,%7,%8,%9,%10,%11,%12,%13,%14,%15,%16};"
        :: "r"(a),
           "r"(r[0]),"r"(r[1]),"r"(r[2]),"r"(r[3]),"r"(r[4]),"r"(r[5]),"r"(r[6]),"r"(r[7]),
           "r"(r[8]),"r"(r[9]),"r"(r[10]),"r"(r[11]),"r"(r[12]),"r"(r[13]),"r"(r[14]),"r"(r[15])
        : "memory");
}
__device__ __forceinline__ void ldtm_x16(uint32_t* r, uint32_t a) {
    asm volatile("tcgen05.ld.sync.aligned.32x32b.x16.b32 "
        "{%0,%1,%2,%3,%4,%5,%6,%7,%8,%9,%10,%11,%12,%13,%14,%15}, [%16];"
        : "=r"(r[0]),"=r"(r[1]),"=r"(r[2]),"=r"(r[3]),"=r"(r[4]),"=r"(r[5]),"=r"(r[6]),"=r"(r[7]),
          "=r"(r[8]),"=r"(r[9]),"=r"(r[10]),"=r"(r[11]),"=r"(r[12]),"=r"(r[13]),"=r"(r[14]),"=r"(r[15])
        : "r"(a));
}

// im2col chunk builder: A rounded once to tf32 (hi only), 16 cols per chunk
__device__ __forceinline__ void build_chunk(char* smem, uint32_t tmem_a, int ci, int wid, int lid) {
    const float* xr = (const float*)(smem + SM_X) + ci * HW;
    const int xpos = (wid << 5) + lid;
    uint32_t regs[16];
#pragma unroll
    for (int dx = 0; dx < 16; ++dx) {
        int sx = xpos + dx - 7;
        float v = (dx < 15 && sx >= 0 && sx < HW) ? xr[sx] : 0.f;
        regs[dx] = __float_as_uint(tf32r(v));
    }
    sttm_x16(tmem_a + ((uint32_t)wid << 21), regs);
}
// Filters for one dy into SMEM (SW128): cols 0-15 hi(tf32), 16-31 lo(residual tf32)
__device__ __forceinline__ void build_filt(char* smem, int boff, const float* __restrict__ filters,
                                           int dy, int t) {
    for (int i = t; i < NF * 32; i += 128) {
        int f = i >> 5, col = i & 31, dx = col & 15;
        float v = (dx < 15) ? filters[(f >> 1) * 450 + (f & 1) * 225 + dy * 15 + dx] : 0.f;
        float hi = tf32r(v);
        float val = (col >= 16) ? tf32r(v - hi) : hi;
        *(float*)(smem + boff + SWZ(f * 128 + col * 4)) = val;
    }
}
#endif  // HAS_TCGEN05

// ---------------------------------------------------------------------------
// Kernel A: Gabor conv + magnitude.
// sm_103a: tcgen05 tf32 TS-mode implicit GEMM, 2-term split D = Ahi x (Bhi+Blo).
// SINGLE ROUND: all 18 A chunks in TMEM, all 15 B slots in SMEM, one commit,
// one wait. No ring, no pipeline, no per-dy sync.
// grid (32 row-groups, 128 planes), 256 threads, occ 1 (TMEM-gated)
// ---------------------------------------------------------------------------
__global__ __launch_bounds__(256, 1)
void gabor_mma_kernel(const float* __restrict__ x, const float* __restrict__ filters) {
#if HAS_TCGEN05
    extern __shared__ char smem[];
    const uint32_t sb = smem_u32(smem);
    const int tid = threadIdx.x, wid = tid >> 5, lid = tid & 31;
    const int plane = blockIdx.y;
    const int y0 = blockIdx.x * RT;
    const int b = plane >> 5, c = plane & 31;

    // stage x + mbar init + B builds BEFORE tmem_alloc (overlaps with the
    // previous resident CTA's tenure; this CTA blocks only at alloc).
    const float* xp = x + (size_t)plane * PLANE;
    float* xs = (float*)(smem + SM_X);
    for (int i = tid; i < NCHUNK * HW; i += 256) {
        int rr = i >> 7, cc = i & 127;
        int gy = y0 + rr - 7;
        xs[i] = (gy >= 0 && gy < HW) ? xp[gy * HW + cc] : 0.f;
    }
    if (tid == 0) mbar_init(sb + SM_MBAR, 1);
    // B builds don't touch TMEM — do them pre-alloc too (warps 4-7)
    if (wid >= 4)
        for (int dy = 0; dy < KK; ++dy)
            build_filt(smem, SM_B + dy * SLOT_BF, filters, dy, tid - 128);
    __syncthreads();

    if (wid == 0) tmem_alloc(sb + SM_TMEM, 512);
    __syncthreads();
    uint32_t tmem;
    asm volatile("ld.shared.b32 %0, [%1];" : "=r"(tmem) : "r"(sb + SM_TMEM));
    if (wid == 0) tmem_relinq();

    // build ALL 18 A chunks into TMEM (warps 0-3; no slot reuse ever)
    if (wid < 4) {
        for (int ci = 0; ci < NCHUNK; ++ci)
            build_chunk(smem, tmem + TM_A0 + ci * 16, ci, wid, lid);
        tc_wait_st();
    }
    tc_fence_before();
    fence_async_shared();
    __syncthreads();

    // single issue burst: 240 MMAs, one commit
    if (wid == 0) {
        tc_fence_after();
        if (elect1()) {
            for (int dy = 0; dy < KK; ++dy) {
                uint64_t bd = mkdesc(sb + SM_B + dy * SLOT_BF);
#pragma unroll
                for (int r = 0; r < RT; ++r) {
                    uint32_t a = tmem + TM_A0 + (dy + r) * 16;
                    uint32_t d = tmem + r * TM_DSTRIDE;
                    mma_tf32_ts(d, a + 0, bd + 0, dy > 0);  // Ahi x Bhi, k0
                    mma_tf32_ts(d, a + 8, bd + 2, 1);       // Ahi x Bhi, k1
                    mma_tf32_ts(d, a + 0, bd + 4, 1);       // Ahi x Blo, k0
                    mma_tf32_ts(d, a + 8, bd + 6, 1);       // Ahi x Blo, k1
                }
            }
            mma_commit(sb + SM_MBAR);
        }
    }
    mbar_wait(sb + SM_MBAR, 0);
    tc_fence_after();

    // epilogue: warps 0-3 -> tiles 0,1 ; warps 4-7 -> tiles 2,3 ; sub = wid&3
    const int sub = wid & 3;
    const int xc = sub * 32 + lid;
    const size_t mbase = ((size_t)b * CIN + (size_t)c * NSO) * PLANE + xc;
#pragma unroll
    for (int rr = 0; rr < 2; ++rr) {
        const int r = (wid >> 2) * 2 + rr;
        uint32_t rg[48];
        ldtm_x16(rg,      tmem + r * TM_DSTRIDE);
        ldtm_x16(rg + 16, tmem + r * TM_DSTRIDE + 16);
        ldtm_x16(rg + 32, tmem + r * TM_DSTRIDE + 32);
        tc_wait_ld();
        const int y = y0 + r;
#pragma unroll
        for (int s = 0; s < NSO; ++s) {
            float re = __uint_as_float(rg[2 * s]);
            float im = __uint_as_float(rg[2 * s + 1]);
            g_mag[mbase + (size_t)s * PLANE + (size_t)y * HW] = sqrtf(re * re + im * im);
        }
    }
    __syncthreads();
    if (tid == 0) mbar_inval(sb + SM_MBAR);
    __syncthreads();
    if (wid == 0) tmem_dealloc(tmem, 512);

#else  // ---------------- scalar FFMA2 fallback (non-arch-specific pass) -----
    extern __shared__ float smf[];
    float* fs = smf;                        // [225][48]
    float* xs = smf + 225 * NF;             // [18][144]
    const int XW = 144;
    const int tid = threadIdx.x;
    const int plane = blockIdx.y;
    const int y0 = blockIdx.x * RT;
    const int b = plane >> 5, c = plane & 31;

    for (int i = tid; i < 225 * NF; i += 256) {
        int tap = i / NF, f = i - tap * NF;
        fs[i] = filters[(f >> 1) * 450 + (f & 1) * 225 + tap];
    }
    const float* xp = x + (size_t)plane * PLANE;
    for (int i = tid; i < NCHUNK * XW; i += 256) {
        int rr = i / XW, cc = i - rr * XW;
        int gy = y0 + rr - 7, gx = cc - 7;
        xs[i] = (gy >= 0 && gy < HW && gx >= 0 && gx < HW) ? xp[gy * HW + gx] : 0.f;
    }
    __syncthreads();

    const int x0 = (tid & 63) * 2;
    const int ry = tid >> 6;
    const size_t mbase0 = ((size_t)b * CIN + (size_t)c * NSO) * PLANE
                        + (size_t)(y0 + ry) * HW + x0;
    for (int g = 0; g < 4; ++g) {
        u64 acc[2][6];
#pragma unroll
        for (int p = 0; p < 2; ++p)
#pragma unroll
            for (int s = 0; s < 6; ++s) acc[p][s] = 0ull;
        for (int dy = 0; dy < KK; ++dy) {
            const float* xr = xs + (ry + dy) * XW + x0;
            const float* wr = fs + dy * KK * NF + g * 12;
#pragma unroll
            for (int dx = 0; dx < KK; ++dx) {
                const float* w = wr + dx * NF;
                ulonglong2 wa = *(const ulonglong2*)(w);
                ulonglong2 wb = *(const ulonglong2*)(w + 4);
                ulonglong2 wc = *(const ulonglong2*)(w + 8);
                u64 wp[6] = {wa.x, wa.y, wb.x, wb.y, wc.x, wc.y};
                u64 xv[2] = {splat(xr[dx]), splat(xr[dx + 1])};
#pragma unroll
                for (int p = 0; p < 2; ++p)
#pragma unroll
                    for (int s = 0; s < 6; ++s) fma2(acc[p][s], xv[p], wp[s]);
            }
        }
#pragma unroll
        for (int s = 0; s < 6; ++s) {
            float re0, im0, re1, im1;
            upk2(acc[0][s], re0, im0);
            upk2(acc[1][s], re1, im1);
            float2 m = make_float2(sqrtf(re0*re0 + im0*im0), sqrtf(re1*re1 + im1*im1));
            *(float2*)(g_mag + mbase0 + (size_t)(g * 6 + s) * PLANE) = m;
        }
    }
#endif
}

// ---------------------------------------------------------------------------
// Kernel B: channel mix (FFMA2), bias dropped (cancels in instance norm)
// ---------------------------------------------------------------------------
static const int SMEM_MIX = CIN * 32 * 4;

__global__ __launch_bounds__(256, 2)
void mix_kernel(const float* __restrict__ w1) {
    extern __shared__ float w1s[];
    const int tid = threadIdx.x;
    for (int i = tid; i < CIN * 32; i += 256) {
        int j = i >> 5, o = i & 31;
        w1s[i] = w1[o * CIN + j];
    }
    __syncthreads();

    const int bb = blockIdx.y;
    const int q0 = blockIdx.x * 512 + tid * 2;
    const float* mp = g_mag + (size_t)bb * CIN * PLANE + q0;

    u64 acc[16][2];
#pragma unroll
    for (int op = 0; op < 16; ++op) { acc[op][0] = 0ull; acc[op][1] = 0ull; }

#pragma unroll 4
    for (int j = 0; j < CIN; ++j) {
        float2 m = *(const float2*)(mp + (size_t)j * PLANE);
        u64 mx = splat(m.x), my = splat(m.y);
        const ulonglong2* wrow = (const ulonglong2*)(w1s + j * 32);
#pragma unroll
        for (int q4 = 0; q4 < 8; ++q4) {
            ulonglong2 w2 = wrow[q4];
            fma2(acc[q4 * 2 + 0][0], mx, w2.x);
            fma2(acc[q4 * 2 + 0][1], my, w2.x);
            fma2(acc[q4 * 2 + 1][0], mx, w2.y);
            fma2(acc[q4 * 2 + 1][1], my, w2.y);
        }
    }
#pragma unroll
    for (int op = 0; op < 16; ++op) {
        float a0lo, a0hi, a1lo, a1hi;
        upk2(acc[op][0], a0lo, a0hi);
        upk2(acc[op][1], a1lo, a1hi);
        *(float2*)(g_z + (size_t)(bb * 32 + 2 * op)     * PLANE + q0) = make_float2(a0lo, a1lo);
        *(float2*)(g_z + (size_t)(bb * 32 + 2 * op + 1) * PLANE + q0) = make_float2(a0hi, a1hi);
    }
}

// ---------------------------------------------------------------------------
__global__ void stats_kernel() {
    const int plane = blockIdx.x;
    const float* zp = g_z + (size_t)plane * PLANE;
    const int tid = threadIdx.x;
    float s = 0.f, s2 = 0.f;
    for (int i = tid * 4; i < PLANE; i += 1024) {
        float4 v = *(const float4*)(zp + i);
        s  += v.x + v.y + v.z + v.w;
        s2 += v.x * v.x + v.y * v.y + v.z * v.z + v.w * v.w;
    }
    __shared__ float r1[256], r2[256];
    r1[tid] = s; r2[tid] = s2;
    __syncthreads();
    for (int st = 128; st > 0; st >>= 1) {
        if (tid < st) { r1[tid] += r1[tid + st]; r2[tid] += r2[tid + st]; }
        __syncthreads();
    }
    if (tid == 0) {
        float mean = r1[0] * (1.f / PLANE);
        float var  = r2[0] * (1.f / PLANE) - mean * mean;
        g_stats[plane * 2]     = mean;
        g_stats[plane * 2 + 1] = rsqrtf(var + 1e-5f);
    }
}

__global__ void norm_kernel(float* __restrict__ out) {
    __shared__ float s[32][33];
    const int plane = blockIdx.y;
    const int tile  = blockIdx.x;
    const int hb = (tile >> 2) * 32, wb = (tile & 3) * 32;
    const float mean = g_stats[plane * 2];
    const float rstd = g_stats[plane * 2 + 1];
    const float* zp = g_z + (size_t)plane * PLANE;
    float* op = out + (size_t)plane * PLANE;
    const int cc = threadIdx.x & 31;
    const int r0 = threadIdx.x >> 5;
#pragma unroll
    for (int k = 0; k < 4; ++k) {
        int rr = r0 + k * 8;
        s[rr][cc] = zp[(wb + rr) * HW + hb + cc];
    }
    __syncthreads();
#pragma unroll
    for (int k = 0; k < 4; ++k) {
        int rr = r0 + k * 8;
        op[(hb + rr) * HW + wb + cc] = (s[cc][rr] - mean) * rstd;
    }
}

// ---------------------------------------------------------------------------
extern "C" void kernel_launch(void* const* d_in, const int* in_sizes, int n_in,
                              void* d_out, int out_size) {
    const float* x       = (const float*)d_in[0];
    const float* filters = (const float*)d_in[1];
    const float* w1      = (const float*)d_in[2];
    float* out = (float*)d_out;

    cudaFuncSetAttribute(gabor_mma_kernel, cudaFuncAttributeMaxDynamicSharedMemorySize, SMEM_GABOR);
    cudaFuncSetAttribute(mix_kernel,       cudaFuncAttributeMaxDynamicSharedMemorySize, SMEM_MIX);

    gabor_mma_kernel<<<dim3(32, 128), 256, SMEM_GABOR>>>(x, filters);
    mix_kernel<<<dim3(32, 4), 256, SMEM_MIX>>>(w1);
    stats_kernel<<<128, 256>>>();
    norm_kernel<<<dim3(16, 128), 256>>>(out);
}